// round 11
// baseline (speedup 1.0000x reference)
#include <cuda_runtime.h>
#include <cuda_bf16.h>
#include <stdint.h>

#define CB 4
#define CS 1500
#define CHID 1024
#define CNH 16
#define CDH 64
#define NREL 129           // 2K+1, K=64
#define MROWS (CB*CS)      // 6000

// ---------------- scratch (device globals; no allocation allowed) -------------
__device__ float g_q[CB*CNH*CS*CDH];       // [B,NH,S,DH]
__device__ float g_k[CB*CNH*CS*CDH];
__device__ float g_v[CB*CNH*CS*CDH];
__device__ float g_hidden[CB*CS*CHID];     // [B,S,HID] concat-head output
// bf16 split-precision staging (reused sequentially across GEMMs)
__device__ __align__(16) __nv_bfloat16 g_xh[MROWS*CHID];
__device__ __align__(16) __nv_bfloat16 g_xl[MROWS*CHID];
__device__ __align__(16) __nv_bfloat16 g_wh[CHID*CHID];   // [N=1024 rows][K=1024] K-major
__device__ __align__(16) __nv_bfloat16 g_wl[CHID*CHID];

// ============================================================================
// Warp-level MMA helpers (base-PTX, legal on compute_103)
// ============================================================================
__device__ __forceinline__ uint32_t smem_u32(const void* p) {
    uint32_t a;
    asm("{ .reg .u64 t; cvta.to.shared.u64 t, %1; cvt.u32.u64 %0, t; }" : "=r"(a) : "l"(p));
    return a;
}
__device__ __forceinline__ void ldsm4(uint32_t* r, uint32_t a) {
    asm volatile("ldmatrix.sync.aligned.m8n8.x4.shared.b16 {%0,%1,%2,%3}, [%4];"
                 : "=r"(r[0]), "=r"(r[1]), "=r"(r[2]), "=r"(r[3]) : "r"(a));
}
__device__ __forceinline__ void mma16816(float* c, const uint32_t* a, const uint32_t* b) {
    asm volatile(
        "mma.sync.aligned.m16n8k16.row.col.f32.bf16.bf16.f32 "
        "{%0,%1,%2,%3}, {%4,%5,%6,%7}, {%8,%9}, {%0,%1,%2,%3};"
        : "+f"(c[0]), "+f"(c[1]), "+f"(c[2]), "+f"(c[3])
        : "r"(a[0]), "r"(a[1]), "r"(a[2]), "r"(a[3]), "r"(b[0]), "r"(b[1]));
}

// ============================================================================
// Split-precision conversion kernels
// ============================================================================
__global__ void cvt_split(const float* __restrict__ x,
                          __nv_bfloat16* __restrict__ hi, __nv_bfloat16* __restrict__ lo,
                          int n) {
    int i = blockIdx.x * blockDim.x + threadIdx.x;
    if (i < n) {
        float v = x[i];
        __nv_bfloat16 h = __float2bfloat16(v);
        hi[i] = h;
        lo[i] = __float2bfloat16(v - __bfloat162float(h));
    }
}
// proj weight: Wb[col][k] = W[n=col>>6][k][d=col&63]  (stacked heads -> K-major)
__global__ void cvt_w_proj(const float* __restrict__ W,
                           __nv_bfloat16* __restrict__ hi, __nv_bfloat16* __restrict__ lo) {
    int i = blockIdx.x * blockDim.x + threadIdx.x;
    if (i < CHID * CHID) {
        int col = i >> 10, k = i & 1023;
        int n = col >> 6, d = col & 63;
        float v = W[((size_t)n * CHID + k) * CDH + d];
        __nv_bfloat16 h = __float2bfloat16(v);
        hi[i] = h;
        lo[i] = __float2bfloat16(v - __bfloat162float(h));
    }
}
// fc weight: Wb[col][k] = Wfc[k][col]
__global__ void cvt_w_fc(const float* __restrict__ W,
                         __nv_bfloat16* __restrict__ hi, __nv_bfloat16* __restrict__ lo) {
    int i = blockIdx.x * blockDim.x + threadIdx.x;
    if (i < CHID * CHID) {
        int col = i >> 10, k = i & 1023;
        float v = W[(size_t)k * CHID + col];
        __nv_bfloat16 h = __float2bfloat16(v);
        hi[i] = h;
        lo[i] = __float2bfloat16(v - __bfloat162float(h));
    }
}

// ============================================================================
// mma.sync split-bf16 GEMM: C[m0:m0+128, n0:n0+128] = X @ W^T + bias
//   X: [6000,1024] K-major bf16 (hi/lo);  W: [1024 N-rows][1024 K] bf16 (hi/lo)
//   C += Ah*Bh + Ah*Bl + Al*Bh  (fp32 accum; drops only eps^2 term)
// Block 128x128, 8 warps 2x4 (warp tile 64x32), K-chunks of 64.
// MODE 0: proj scatter to [B,NH,S,DH];  MODE 1: plain [M,1024] store
// ============================================================================
#define SPITCH 144                       // 72 bf16 per row (64 data + 8 pad)
#define TILE_BYTES (128 * SPITCH)        // 18432
#define GEMM_SMEM_BYTES (4 * TILE_BYTES) // 73728: Ah, Al, Bh, Bl

template<int MODE>
__global__ __launch_bounds__(256, 1) void gemm_mma(
    const __nv_bfloat16* __restrict__ Xh, const __nv_bfloat16* __restrict__ Xl,
    const __nv_bfloat16* __restrict__ Wh, const __nv_bfloat16* __restrict__ Wl,
    const float* __restrict__ bias, float* __restrict__ out)
{
    extern __shared__ char smem[];
    uint32_t sbase = smem_u32(smem);
    int tid = threadIdx.x;
    int wid = tid >> 5, lid = tid & 31;
    int wm = wid & 1, wn = wid >> 1;     // 2 x 4 warp grid
    int m0 = blockIdx.x * 128;
    int n0 = blockIdx.y * 128;

    float C[4][4][4];                     // [mfrag][nfrag][c0..c3]
    #pragma unroll
    for (int i = 0; i < 4; i++)
        #pragma unroll
        for (int j = 0; j < 4; j++)
            #pragma unroll
            for (int r = 0; r < 4; r++) C[i][j][r] = 0.f;

    // precomputed ldmatrix smem addresses (lane-dependent, chunk-invariant)
    // A tiles: row = wm*64 + i*16 + (lid&15), koff8 = (lid>>4)*8
    uint32_t a_row = wm * 64 + (lid & 15);
    uint32_t a_koff = (lid >> 4) * 8;
    // B tiles (x4 covers 2 nfrags): t = lid>>3
    uint32_t b_n = wn * 32 + ((lid >> 4) * 8) + (lid & 7); // lanes16+ -> +8 rows
    uint32_t b_koff = ((lid >> 3) & 1) * 8;

    const int NCHUNK = CHID / 64;        // 16
    for (int c = 0; c < NCHUNK; c++) {
        __syncthreads();
        // ---- load 4 tiles: 128 rows x 64 bf16, padded rows ----
        #pragma unroll
        for (int t = 0; t < 4; t++) {
            const __nv_bfloat16* src = (t == 0) ? Xh : (t == 1) ? Xl : (t == 2) ? Wh : Wl;
            const bool isA = (t < 2);
            char* db = smem + t * TILE_BYTES;
            #pragma unroll
            for (int p = 0; p < 4; p++) {
                int slot = tid + p * 256;            // 0..1023
                int row = slot >> 3, i8 = slot & 7;
                int gr = (isA ? m0 : n0) + row;
                uint4 v = make_uint4(0, 0, 0, 0);
                if (!isA || gr < MROWS)
                    v = ((const uint4*)(src + (size_t)gr * CHID + c * 64))[i8];
                *(uint4*)(db + row * SPITCH + i8 * 16) = v;
            }
        }
        __syncthreads();

        // ---- 4 k16 steps ----
        #pragma unroll
        for (int ks = 0; ks < 4; ks++) {
            uint32_t Ah[4][4], Al[4][4], Bh[4][2], Bl[4][2];
            #pragma unroll
            for (int i = 0; i < 4; i++) {
                uint32_t off = (a_row + i * 16) * SPITCH + (ks * 16 + a_koff) * 2;
                ldsm4(Ah[i], sbase + 0 * TILE_BYTES + off);
                ldsm4(Al[i], sbase + 1 * TILE_BYTES + off);
            }
            #pragma unroll
            for (int j2 = 0; j2 < 2; j2++) {
                uint32_t off = (b_n + j2 * 16) * SPITCH + (ks * 16 + b_koff) * 2;
                uint32_t tmp[4];
                ldsm4(tmp, sbase + 2 * TILE_BYTES + off);
                Bh[j2 * 2][0] = tmp[0]; Bh[j2 * 2][1] = tmp[1];
                Bh[j2 * 2 + 1][0] = tmp[2]; Bh[j2 * 2 + 1][1] = tmp[3];
                ldsm4(tmp, sbase + 3 * TILE_BYTES + off);
                Bl[j2 * 2][0] = tmp[0]; Bl[j2 * 2][1] = tmp[1];
                Bl[j2 * 2 + 1][0] = tmp[2]; Bl[j2 * 2 + 1][1] = tmp[3];
            }
            #pragma unroll
            for (int i = 0; i < 4; i++)
                #pragma unroll
                for (int j = 0; j < 4; j++) {
                    mma16816(C[i][j], Ah[i], Bh[j]);
                    mma16816(C[i][j], Ah[i], Bl[j]);
                    mma16816(C[i][j], Al[i], Bh[j]);
                }
        }
    }

    // ---- epilogue: fused bias + (MODE 0) head scatter ----
    int r = lid >> 2, cg = (lid & 3) * 2;
    #pragma unroll
    for (int i = 0; i < 4; i++) {
        int row0 = m0 + wm * 64 + i * 16 + r;
        int row1 = row0 + 8;
        #pragma unroll
        for (int j = 0; j < 4; j++) {
            int col = n0 + wn * 32 + j * 8 + cg;
            float b0 = bias[col], b1 = bias[col + 1];
            float2 v0 = make_float2(C[i][j][0] + b0, C[i][j][1] + b1);
            float2 v1 = make_float2(C[i][j][2] + b0, C[i][j][3] + b1);
            if (MODE == 0) {
                int n = col >> 6, d = col & 63;
                if (row0 < MROWS) {
                    int bi = row0 / CS, s = row0 - bi * CS;
                    *(float2*)(out + (((size_t)(bi * CNH + n)) * CS + s) * CDH + d) = v0;
                }
                if (row1 < MROWS) {
                    int bi = row1 / CS, s = row1 - bi * CS;
                    *(float2*)(out + (((size_t)(bi * CNH + n)) * CS + s) * CDH + d) = v1;
                }
            } else {
                if (row0 < MROWS) *(float2*)(out + (size_t)row0 * CHID + col) = v0;
                if (row1 < MROWS) *(float2*)(out + (size_t)row1 * CHID + col) = v1;
            }
        }
    }
}

// ============================================================================
// Flash attention with Shaw relative position bias (unchanged from R3 pass).
// ============================================================================
#define SQ_STRIDE 68
#define SR_STRIDE 132
#define FLASH_SMEM_FLOATS (4*64*SQ_STRIDE + 64*SR_STRIDE)

__global__ __launch_bounds__(256, 2) void flash_kernel(
    const float* __restrict__ posk, const float* __restrict__ posv)
{
    extern __shared__ float sm[];
    float* Qs  = sm;                              // [64][68]
    float* Rs  = Qs + 64 * SQ_STRIDE;             // [64][132]
    float* Ks  = Rs + 64 * SR_STRIDE;             // [64][68]
    float* Vs  = Ks + 64 * SQ_STRIDE;             // [64][68]
    float* Ps  = Vs + 64 * SQ_STRIDE;             // [64][68]
    float* PKs = Ks;                              // prologue overlay [129][68]

    int qt = blockIdx.x, hn = blockIdx.y, bb = blockIdx.z;
    int q0 = qt * 64;
    size_t head_off = ((size_t)(bb * CNH + hn)) * CS * CDH;
    const float* qbase = g_q + head_off;
    const float* kbase = g_k + head_off;
    const float* vbase = g_v + head_off;

    int tid = threadIdx.x;
    int tx = tid & 15, ty = tid >> 4;

    for (int idx = tid; idx < 64 * 64; idx += 256) {
        int r = idx >> 6, d = idx & 63;
        int qg = q0 + r;
        Qs[r * SQ_STRIDE + d] = (qg < CS) ? qbase[qg * CDH + d] : 0.f;
    }
    for (int idx = tid; idx < NREL * 64; idx += 256) {
        int j = idx >> 6, d = idx & 63;
        PKs[j * SQ_STRIDE + d] = posk[idx];
    }
    __syncthreads();

    for (int t = tid; t < 64 * 33; t += 256) {
        int qq = t / 33;
        int jg = t - qq * 33;
        int j0 = jg * 4;
        const float4* q4 = (const float4*)(Qs + qq * SQ_STRIDE);
        if (jg < 32) {
            const float4* p0 = (const float4*)(PKs + (j0 + 0) * SQ_STRIDE);
            const float4* p1 = (const float4*)(PKs + (j0 + 1) * SQ_STRIDE);
            const float4* p2 = (const float4*)(PKs + (j0 + 2) * SQ_STRIDE);
            const float4* p3 = (const float4*)(PKs + (j0 + 3) * SQ_STRIDE);
            float a0 = 0.f, a1 = 0.f, a2 = 0.f, a3 = 0.f;
            #pragma unroll
            for (int d4 = 0; d4 < 16; d4++) {
                float4 qv = q4[d4];
                float4 x;
                x = p0[d4]; a0 += qv.x*x.x + qv.y*x.y + qv.z*x.z + qv.w*x.w;
                x = p1[d4]; a1 += qv.x*x.x + qv.y*x.y + qv.z*x.z + qv.w*x.w;
                x = p2[d4]; a2 += qv.x*x.x + qv.y*x.y + qv.z*x.z + qv.w*x.w;
                x = p3[d4]; a3 += qv.x*x.x + qv.y*x.y + qv.z*x.z + qv.w*x.w;
            }
            Rs[qq * SR_STRIDE + j0 + 0] = a0;
            Rs[qq * SR_STRIDE + j0 + 1] = a1;
            Rs[qq * SR_STRIDE + j0 + 2] = a2;
            Rs[qq * SR_STRIDE + j0 + 3] = a3;
        } else {
            const float4* p0 = (const float4*)(PKs + 128 * SQ_STRIDE);
            float a0 = 0.f;
            #pragma unroll
            for (int d4 = 0; d4 < 16; d4++) {
                float4 qv = q4[d4];
                float4 x = p0[d4];
                a0 += qv.x*x.x + qv.y*x.y + qv.z*x.z + qv.w*x.w;
            }
            Rs[qq * SR_STRIDE + 128] = a0;
        }
    }

    float m_i[4], l_i[4], PL[4], PH[4], O[4][4];
    #pragma unroll
    for (int i = 0; i < 4; i++) {
        m_i[i] = -1e30f; l_i[i] = 0.f; PL[i] = 0.f; PH[i] = 0.f;
        #pragma unroll
        for (int j = 0; j < 4; j++) O[i][j] = 0.f;
    }

    const int NKT = (CS + 63) / 64;
    for (int kt = 0; kt < NKT; kt++) {
        __syncthreads();
        for (int idx = tid; idx < 64 * 64; idx += 256) {
            int r = idx >> 6, d = idx & 63;
            int kg = kt * 64 + r;
            float kv = 0.f, vv = 0.f;
            if (kg < CS) { kv = kbase[kg * CDH + d]; vv = vbase[kg * CDH + d]; }
            Ks[r * SQ_STRIDE + d] = kv;
            Vs[r * SQ_STRIDE + d] = vv;
        }
        __syncthreads();

        float s[4][4];
        #pragma unroll
        for (int i = 0; i < 4; i++)
            #pragma unroll
            for (int j = 0; j < 4; j++) s[i][j] = 0.f;
        #pragma unroll 8
        for (int d = 0; d < 64; d++) {
            float a[4], bv[4];
            #pragma unroll
            for (int i = 0; i < 4; i++) a[i] = Qs[(ty * 4 + i) * SQ_STRIDE + d];
            #pragma unroll
            for (int j = 0; j < 4; j++) bv[j] = Ks[(tx * 4 + j) * SQ_STRIDE + d];
            #pragma unroll
            for (int i = 0; i < 4; i++)
                #pragma unroll
                for (int j = 0; j < 4; j++) s[i][j] += a[i] * bv[j];
        }

        #pragma unroll
        for (int i = 0; i < 4; i++) {
            int qg = q0 + ty * 4 + i;
            #pragma unroll
            for (int j = 0; j < 4; j++) {
                int kg = kt * 64 + tx * 4 + j;
                int delta = kg - qg;
                int jc = delta < -64 ? 0 : (delta > 64 ? 128 : delta + 64);
                float val = (s[i][j] + Rs[(ty * 4 + i) * SR_STRIDE + jc]) * 0.125f;
                s[i][j] = (kg < CS) ? val : -1e30f;
            }
        }

        int diff = kt * 64 - q0;
        bool band = (diff >= -64 && diff <= 64);

        #pragma unroll
        for (int i = 0; i < 4; i++) {
            float tmax = fmaxf(fmaxf(s[i][0], s[i][1]), fmaxf(s[i][2], s[i][3]));
            #pragma unroll
            for (int off = 8; off >= 1; off >>= 1)
                tmax = fmaxf(tmax, __shfl_xor_sync(0xffffffffu, tmax, off));
            float mnew  = fmaxf(m_i[i], tmax);
            float alpha = __expf(m_i[i] - mnew);
            m_i[i] = mnew;
            int qg = q0 + ty * 4 + i;
            float psum = 0.f, plo = 0.f, phi = 0.f;
            #pragma unroll
            for (int j = 0; j < 4; j++) {
                float p = __expf(s[i][j] - mnew);
                s[i][j] = p;
                psum += p;
                if (band) {
                    int delta = (kt * 64 + tx * 4 + j) - qg;
                    if (delta <= -64) plo += p;
                    if (delta >=  64) phi += p;
                }
            }
            #pragma unroll
            for (int off = 8; off >= 1; off >>= 1)
                psum += __shfl_xor_sync(0xffffffffu, psum, off);
            if (band) {
                #pragma unroll
                for (int off = 8; off >= 1; off >>= 1) {
                    plo += __shfl_xor_sync(0xffffffffu, plo, off);
                    phi += __shfl_xor_sync(0xffffffffu, phi, off);
                }
            } else if (diff < -64) { plo = psum; phi = 0.f; }
            else                   { phi = psum; plo = 0.f; }

            l_i[i] = l_i[i] * alpha + psum;
            PL[i]  = PL[i]  * alpha + plo;
            PH[i]  = PH[i]  * alpha + phi;
            #pragma unroll
            for (int j = 0; j < 4; j++) O[i][j] *= alpha;
            #pragma unroll
            for (int j = 0; j < 4; j++)
                Ps[(ty * 4 + i) * SQ_STRIDE + tx * 4 + j] = s[i][j];
        }
        __syncthreads();

        #pragma unroll 8
        for (int kk = 0; kk < 64; kk++) {
            float a[4], v[4];
            #pragma unroll
            for (int i = 0; i < 4; i++) a[i] = Ps[(ty * 4 + i) * SQ_STRIDE + kk];
            #pragma unroll
            for (int j = 0; j < 4; j++) v[j] = Vs[kk * SQ_STRIDE + tx * 4 + j];
            #pragma unroll
            for (int i = 0; i < 4; i++)
                #pragma unroll
                for (int j = 0; j < 4; j++) O[i][j] += a[i] * v[j];
        }

        if (band) {
            #pragma unroll 4
            for (int kk = 0; kk < 64; kk++) {
                int kg = kt * 64 + kk;
                #pragma unroll
                for (int i = 0; i < 4; i++) {
                    int delta = kg - (q0 + ty * 4 + i);
                    if (delta > -64 && delta < 64) {
                        float p = Ps[(ty * 4 + i) * SQ_STRIDE + kk];
                        float4 pv = *(const float4*)(posv + (delta + 64) * 64 + tx * 4);
                        O[i][0] += p * pv.x; O[i][1] += p * pv.y;
                        O[i][2] += p * pv.z; O[i][3] += p * pv.w;
                    }
                }
            }
        }
    }

    #pragma unroll
    for (int i = 0; i < 4; i++) {
        int qg = q0 + ty * 4 + i;
        if (qg >= CS) continue;
        float inv = 1.f / l_i[i];
        int dg = tx * 4;
        float4 pv0   = *(const float4*)(posv + 0 * 64 + dg);
        float4 pv128 = *(const float4*)(posv + 128 * 64 + dg);
        float4 res;
        res.x = (O[i][0] + PL[i] * pv0.x + PH[i] * pv128.x) * inv;
        res.y = (O[i][1] + PL[i] * pv0.y + PH[i] * pv128.y) * inv;
        res.z = (O[i][2] + PL[i] * pv0.z + PH[i] * pv128.z) * inv;
        res.w = (O[i][3] + PL[i] * pv0.w + PH[i] * pv128.w) * inv;
        *(float4*)(g_hidden + ((size_t)(bb * CS + qg)) * CHID + hn * 64 + dg) = res;
    }
}

// ============================================================================
extern "C" void kernel_launch(void* const* d_in, const int* in_sizes, int n_in,
                              void* d_out, int out_size)
{
    const float* query = (const float*)d_in[0];
    const float* key   = (const float*)d_in[1];
    const float* value = (const float*)d_in[2];
    const float* Wq    = (const float*)d_in[3];
    const float* bq    = (const float*)d_in[4];
    const float* Wk    = (const float*)d_in[5];
    const float* bk    = (const float*)d_in[6];
    const float* Wv    = (const float*)d_in[7];
    const float* bv    = (const float*)d_in[8];
    const float* posk  = (const float*)d_in[9];
    const float* posv  = (const float*)d_in[10];
    const float* Wfc   = (const float*)d_in[11];
    const float* bfc   = (const float*)d_in[12];
    float* out = (float*)d_out;

    float *gq, *gk, *gv, *gh;
    __nv_bfloat16 *xh, *xl, *wh, *wl;
    cudaGetSymbolAddress((void**)&gq, g_q);
    cudaGetSymbolAddress((void**)&gk, g_k);
    cudaGetSymbolAddress((void**)&gv, g_v);
    cudaGetSymbolAddress((void**)&gh, g_hidden);
    cudaGetSymbolAddress((void**)&xh, g_xh);
    cudaGetSymbolAddress((void**)&xl, g_xl);
    cudaGetSymbolAddress((void**)&wh, g_wh);
    cudaGetSymbolAddress((void**)&wl, g_wl);

    cudaFuncSetAttribute(gemm_mma<0>, cudaFuncAttributeMaxDynamicSharedMemorySize, GEMM_SMEM_BYTES);
    cudaFuncSetAttribute(gemm_mma<1>, cudaFuncAttributeMaxDynamicSharedMemorySize, GEMM_SMEM_BYTES);

    const int nX = MROWS * CHID;
    const int nW = CHID * CHID;
    dim3 ggrid((MROWS + 127) / 128, CHID / 128);   // 47 x 8

    // Q projection
    cvt_split<<<(nX + 255) / 256, 256>>>(query, xh, xl, nX);
    cvt_w_proj<<<(nW + 255) / 256, 256>>>(Wq, wh, wl);
    gemm_mma<0><<<ggrid, 256, GEMM_SMEM_BYTES>>>(xh, xl, wh, wl, bq, gq);
    // K projection
    cvt_split<<<(nX + 255) / 256, 256>>>(key, xh, xl, nX);
    cvt_w_proj<<<(nW + 255) / 256, 256>>>(Wk, wh, wl);
    gemm_mma<0><<<ggrid, 256, GEMM_SMEM_BYTES>>>(xh, xl, wh, wl, bk, gk);
    // V projection
    cvt_split<<<(nX + 255) / 256, 256>>>(value, xh, xl, nX);
    cvt_w_proj<<<(nW + 255) / 256, 256>>>(Wv, wh, wl);
    gemm_mma<0><<<ggrid, 256, GEMM_SMEM_BYTES>>>(xh, xl, wh, wl, bv, gv);

    // attention
    int smem_bytes = FLASH_SMEM_FLOATS * (int)sizeof(float);   // 103,424 B
    cudaFuncSetAttribute(flash_kernel,
                         cudaFuncAttributeMaxDynamicSharedMemorySize, smem_bytes);
    flash_kernel<<<dim3((CS + 63) / 64, CNH, CB), 256, smem_bytes>>>(posk, posv);

    // output projection
    cvt_split<<<(nX + 255) / 256, 256>>>(gh, xh, xl, nX);
    cvt_w_fc<<<(nW + 255) / 256, 256>>>(Wfc, wh, wl);
    gemm_mma<1><<<ggrid, 256, GEMM_SMEM_BYTES>>>(xh, xl, wh, wl, bfc, out);
}

// round 13
// speedup vs baseline: 1.6157x; 1.6157x over previous
#include <cuda_runtime.h>
#include <cuda_bf16.h>
#include <stdint.h>

#define CB 4
#define CS 1500
#define CHID 1024
#define CNH 16
#define CDH 64
#define NREL 129
#define MROWS (CB*CS)      // 6000
#define SPAD 1536          // padded S for V^T rows

// ---------------- scratch (device globals; zero-initialized) ----------------
__device__ __align__(16) __nv_bfloat16 g_qh[CB*CNH*CS*CDH];
__device__ __align__(16) __nv_bfloat16 g_ql[CB*CNH*CS*CDH];
__device__ __align__(16) __nv_bfloat16 g_kh[CB*CNH*CS*CDH];
__device__ __align__(16) __nv_bfloat16 g_kl[CB*CNH*CS*CDH];
__device__ __align__(16) __nv_bfloat16 g_vh[CB*CNH*CDH*SPAD];  // V^T [B,NH,DH,SPAD]
__device__ __align__(16) __nv_bfloat16 g_vl[CB*CNH*CDH*SPAD];
__device__ __align__(16) __nv_bfloat16 g_xh[MROWS*CHID];       // GEMM A / hidden
__device__ __align__(16) __nv_bfloat16 g_xl[MROWS*CHID];
__device__ __align__(16) __nv_bfloat16 g_wh[CHID*CHID];
__device__ __align__(16) __nv_bfloat16 g_wl[CHID*CHID];

// ---------------- helpers ----------------
__device__ __forceinline__ uint32_t smem_u32(const void* p) {
    uint32_t a;
    asm("{ .reg .u64 t; cvta.to.shared.u64 t, %1; cvt.u32.u64 %0, t; }" : "=r"(a) : "l"(p));
    return a;
}
__device__ __forceinline__ void ldsm4(uint32_t* r, uint32_t a) {
    asm volatile("ldmatrix.sync.aligned.m8n8.x4.shared.b16 {%0,%1,%2,%3}, [%4];"
                 : "=r"(r[0]), "=r"(r[1]), "=r"(r[2]), "=r"(r[3]) : "r"(a));
}
__device__ __forceinline__ void mma16816(float* c, const uint32_t* a, const uint32_t* b) {
    asm volatile(
        "mma.sync.aligned.m16n8k16.row.col.f32.bf16.bf16.f32 "
        "{%0,%1,%2,%3}, {%4,%5,%6,%7}, {%8,%9}, {%0,%1,%2,%3};"
        : "+f"(c[0]), "+f"(c[1]), "+f"(c[2]), "+f"(c[3])
        : "r"(a[0]), "r"(a[1]), "r"(a[2]), "r"(a[3]), "r"(b[0]), "r"(b[1]));
}
// FFMA-only exp (no MUFU). valid for x <= 0, exact-ish, clamped at 2^-120.
__device__ __forceinline__ float fexp(float x) {
    float y = fmaxf(x * 1.4426950408889634f, -120.0f);
    float z = y + 12582912.0f;
    int   i = __float_as_int(z) - 0x4B400000;
    float f = y - (z - 12582912.0f);
    float p =      1.3333558146e-3f;
    p = fmaf(p, f, 9.6181291076e-3f);
    p = fmaf(p, f, 5.5504108665e-2f);
    p = fmaf(p, f, 2.4022650696e-1f);
    p = fmaf(p, f, 6.9314718056e-1f);
    p = fmaf(p, f, 1.0f);
    return __int_as_float(__float_as_int(p) + (i << 23));
}
__device__ __forceinline__ uint32_t packbf(float a, float b) {
    __nv_bfloat162 t = __halves2bfloat162(__float2bfloat16(a), __float2bfloat16(b));
    return *(uint32_t*)&t;
}

// ---------------- conversion kernels ----------------
__global__ void cvt_split(const float* __restrict__ x,
                          __nv_bfloat16* __restrict__ hi, __nv_bfloat16* __restrict__ lo, int n) {
    int i = blockIdx.x * blockDim.x + threadIdx.x;
    if (i < n) {
        float v = x[i];
        __nv_bfloat16 h = __float2bfloat16(v);
        hi[i] = h; lo[i] = __float2bfloat16(v - __bfloat162float(h));
    }
}
__global__ void cvt_w_proj(const float* __restrict__ W,
                           __nv_bfloat16* __restrict__ hi, __nv_bfloat16* __restrict__ lo) {
    int i = blockIdx.x * blockDim.x + threadIdx.x;
    if (i < CHID * CHID) {
        int col = i >> 10, k = i & 1023;
        float v = W[((size_t)(col >> 6) * CHID + k) * CDH + (col & 63)];
        __nv_bfloat16 h = __float2bfloat16(v);
        hi[i] = h; lo[i] = __float2bfloat16(v - __bfloat162float(h));
    }
}
__global__ void cvt_w_fc(const float* __restrict__ W,
                         __nv_bfloat16* __restrict__ hi, __nv_bfloat16* __restrict__ lo) {
    int i = blockIdx.x * blockDim.x + threadIdx.x;
    if (i < CHID * CHID) {
        int col = i >> 10, k = i & 1023;
        float v = W[(size_t)k * CHID + col];
        __nv_bfloat16 h = __float2bfloat16(v);
        hi[i] = h; lo[i] = __float2bfloat16(v - __bfloat162float(h));
    }
}

// ============================================================================
// mma.sync split-bf16 GEMM (R7-validated core).
// MODE 0: bf16 hi/lo scatter [B,NH,S,DH]; MODE 2: bf16 hi/lo V^T [B,NH,DH,SPAD];
// MODE 3: fp32 [M,CHID]
// ============================================================================
#define SPITCH 144
#define TILE_BYTES (128 * SPITCH)
#define GEMM_SMEM_BYTES (4 * TILE_BYTES)

template<int MODE>
__global__ __launch_bounds__(256, 1) void gemm_mma(
    const __nv_bfloat16* __restrict__ Xh, const __nv_bfloat16* __restrict__ Xl,
    const __nv_bfloat16* __restrict__ Wh, const __nv_bfloat16* __restrict__ Wl,
    const float* __restrict__ bias, float* __restrict__ outf,
    __nv_bfloat16* __restrict__ oh, __nv_bfloat16* __restrict__ ol)
{
    extern __shared__ char smem[];
    uint32_t sbase = smem_u32(smem);
    int tid = threadIdx.x, wid = tid >> 5, lid = tid & 31;
    int wm = wid & 1, wn = wid >> 1;
    int m0 = blockIdx.x * 128, n0 = blockIdx.y * 128;

    float C[4][4][4];
    #pragma unroll
    for (int i = 0; i < 4; i++)
        #pragma unroll
        for (int j = 0; j < 4; j++)
            #pragma unroll
            for (int r = 0; r < 4; r++) C[i][j][r] = 0.f;

    uint32_t a_row = wm * 64 + (lid & 15), a_koff = (lid >> 4) * 8;
    uint32_t b_n = wn * 32 + ((lid >> 4) * 8) + (lid & 7);
    uint32_t b_koff = ((lid >> 3) & 1) * 8;

    for (int c = 0; c < CHID / 64; c++) {
        __syncthreads();
        #pragma unroll
        for (int t = 0; t < 4; t++) {
            const __nv_bfloat16* src = (t == 0) ? Xh : (t == 1) ? Xl : (t == 2) ? Wh : Wl;
            const bool isA = (t < 2);
            char* db = smem + t * TILE_BYTES;
            #pragma unroll
            for (int p = 0; p < 4; p++) {
                int slot = tid + p * 256;
                int row = slot >> 3, i8 = slot & 7;
                int gr = (isA ? m0 : n0) + row;
                uint4 v = make_uint4(0, 0, 0, 0);
                if (!isA || gr < MROWS)
                    v = ((const uint4*)(src + (size_t)gr * CHID + c * 64))[i8];
                *(uint4*)(db + row * SPITCH + i8 * 16) = v;
            }
        }
        __syncthreads();
        #pragma unroll
        for (int ks = 0; ks < 4; ks++) {
            uint32_t Ah[4][4], Al[4][4], Bh[4][2], Bl[4][2];
            #pragma unroll
            for (int i = 0; i < 4; i++) {
                uint32_t off = (a_row + i * 16) * SPITCH + (ks * 16 + a_koff) * 2;
                ldsm4(Ah[i], sbase + 0 * TILE_BYTES + off);
                ldsm4(Al[i], sbase + 1 * TILE_BYTES + off);
            }
            #pragma unroll
            for (int j2 = 0; j2 < 2; j2++) {
                uint32_t off = (b_n + j2 * 16) * SPITCH + (ks * 16 + b_koff) * 2;
                uint32_t tmp[4];
                ldsm4(tmp, sbase + 2 * TILE_BYTES + off);
                Bh[j2*2][0] = tmp[0]; Bh[j2*2][1] = tmp[1];
                Bh[j2*2+1][0] = tmp[2]; Bh[j2*2+1][1] = tmp[3];
                ldsm4(tmp, sbase + 3 * TILE_BYTES + off);
                Bl[j2*2][0] = tmp[0]; Bl[j2*2][1] = tmp[1];
                Bl[j2*2+1][0] = tmp[2]; Bl[j2*2+1][1] = tmp[3];
            }
            #pragma unroll
            for (int i = 0; i < 4; i++)
                #pragma unroll
                for (int j = 0; j < 4; j++) {
                    mma16816(C[i][j], Ah[i], Bh[j]);
                    mma16816(C[i][j], Ah[i], Bl[j]);
                    mma16816(C[i][j], Al[i], Bh[j]);
                }
        }
    }
    int r = lid >> 2, cg = (lid & 3) * 2;
    #pragma unroll
    for (int i = 0; i < 4; i++) {
        int rows[2] = { m0 + wm*64 + i*16 + r, m0 + wm*64 + i*16 + r + 8 };
        #pragma unroll
        for (int j = 0; j < 4; j++) {
            int col = n0 + wn * 32 + j * 8 + cg;
            float b0 = bias[col], b1 = bias[col + 1];
            float vx[2] = { C[i][j][0] + b0, C[i][j][2] + b0 };
            float vy[2] = { C[i][j][1] + b1, C[i][j][3] + b1 };
            #pragma unroll
            for (int h = 0; h < 2; h++) {
                int row = rows[h];
                if (row >= MROWS) continue;
                if (MODE == 3) {
                    *(float2*)(outf + (size_t)row * CHID + col) = make_float2(vx[h], vy[h]);
                } else {
                    int bi = row / CS, s = row - bi * CS;
                    int n = col >> 6, d = col & 63;
                    __nv_bfloat16 hx = __float2bfloat16(vx[h]), hy = __float2bfloat16(vy[h]);
                    __nv_bfloat16 lx = __float2bfloat16(vx[h] - __bfloat162float(hx));
                    __nv_bfloat16 ly = __float2bfloat16(vy[h] - __bfloat162float(hy));
                    if (MODE == 0) {
                        size_t a = (((size_t)(bi * CNH + n)) * CS + s) * CDH + d;
                        *(__nv_bfloat162*)(oh + a) = __halves2bfloat162(hx, hy);
                        *(__nv_bfloat162*)(ol + a) = __halves2bfloat162(lx, ly);
                    } else {
                        size_t base = (size_t)(bi * CNH + n) * CDH;
                        oh[(base + d) * SPAD + s] = hx; oh[(base + d + 1) * SPAD + s] = hy;
                        ol[(base + d) * SPAD + s] = lx; ol[(base + d + 1) * SPAD + s] = ly;
                    }
                }
            }
        }
    }
}

// ============================================================================
// Tensor-core flash attention + Shaw bias. Block = (qtile64, head, batch).
// 8 warps: wq=wid&3 (16 q-rows), wk=wid>>2 (32 k-cols half). Partial O per half.
// ============================================================================
#define FP 144
#define OQH 0
#define OQL 9216
#define OKH 18432
#define OKL 27648
#define OVH 36864
#define OVL 46080
#define ORS 55296               // fp32 [64][132]
#define OPV 89088               // fp32 [129][68]
#define OPB 124176              // fp32 [64][68]
#define OST 141584              // state
#define FSM 144912

__global__ __launch_bounds__(256, 1) void flash_mma(
    const float* __restrict__ posk, const float* __restrict__ posv)
{
    extern __shared__ char sm[];
    uint32_t sb = smem_u32(sm);
    float* Rs  = (float*)(sm + ORS);
    float* PVt = (float*)(sm + OPV);
    float* Pb  = (float*)(sm + OPB);
    float* ST  = (float*)(sm + OST);
    float *row_m = ST, *row_l = ST + 64, *rPL = ST + 128, *rPH = ST + 192, *ral = ST + 256;
    float *pmax = ST + 320, *psm = ST + 448, *plo = ST + 576, *phi = ST + 704;

    int qt = blockIdx.x, hn = blockIdx.y, bb = blockIdx.z;
    int q0 = qt * 64;
    size_t ho = ((size_t)(bb * CNH + hn)) * CS * CDH;
    size_t hv = ((size_t)(bb * CNH + hn)) * CDH * SPAD;
    int tid = threadIdx.x, wid = tid >> 5, lid = tid & 31;
    int wq = wid & 3, wk = wid >> 2;
    int qr = lid >> 2, qc = (lid & 3) * 2;
    int row0 = wq * 16 + qr, row1 = row0 + 8;
    int qg0 = q0 + row0, qg1 = q0 + row1;

    // ---- prologue: Q tiles, fp32 Q, posk, state ----
    #pragma unroll
    for (int p = 0; p < 2; p++) {
        int slot = tid + p * 256;
        int r = slot >> 3, i8 = slot & 7;
        int qg = q0 + r;
        uint4 vh = make_uint4(0,0,0,0), vl = vh;
        if (qg < CS) {
            vh = ((const uint4*)(g_qh + ho + (size_t)qg * CDH))[i8];
            vl = ((const uint4*)(g_ql + ho + (size_t)qg * CDH))[i8];
        }
        *(uint4*)(sm + OQH + r * FP + i8 * 16) = vh;
        *(uint4*)(sm + OQL + r * FP + i8 * 16) = vl;
    }
    for (int idx = tid; idx < NREL * 64; idx += 256)
        PVt[(idx >> 6) * 68 + (idx & 63)] = posk[idx];
    if (tid < 64) { row_m[tid] = -1e30f; row_l[tid] = 0.f; rPL[tid] = 0.f; rPH[tid] = 0.f; }
    __syncthreads();
    for (int idx = tid; idx < 64 * 64; idx += 256) {
        int r = idx >> 6, d = idx & 63;
        Pb[r * 68 + d] = __bfloat162float(*(__nv_bfloat16*)(sm + OQH + r * FP + d * 2))
                       + __bfloat162float(*(__nv_bfloat16*)(sm + OQL + r * FP + d * 2));
    }
    __syncthreads();
    // Rs[q][j] = Q[q,:].pos_k[j,:]  (R3-proven)
    for (int t = tid; t < 64 * 33; t += 256) {
        int qq = t / 33, jg = t - qq * 33, j0 = jg * 4;
        const float4* q4 = (const float4*)(Pb + qq * 68);
        if (jg < 32) {
            const float4 *p0 = (const float4*)(PVt + (j0+0)*68), *p1 = (const float4*)(PVt + (j0+1)*68);
            const float4 *p2 = (const float4*)(PVt + (j0+2)*68), *p3 = (const float4*)(PVt + (j0+3)*68);
            float a0=0,a1=0,a2=0,a3=0;
            #pragma unroll
            for (int d4 = 0; d4 < 16; d4++) {
                float4 qv = q4[d4]; float4 x;
                x=p0[d4]; a0+=qv.x*x.x+qv.y*x.y+qv.z*x.z+qv.w*x.w;
                x=p1[d4]; a1+=qv.x*x.x+qv.y*x.y+qv.z*x.z+qv.w*x.w;
                x=p2[d4]; a2+=qv.x*x.x+qv.y*x.y+qv.z*x.z+qv.w*x.w;
                x=p3[d4]; a3+=qv.x*x.x+qv.y*x.y+qv.z*x.z+qv.w*x.w;
            }
            Rs[qq*132+j0]=a0; Rs[qq*132+j0+1]=a1; Rs[qq*132+j0+2]=a2; Rs[qq*132+j0+3]=a3;
        } else {
            const float4* p0 = (const float4*)(PVt + 128 * 68);
            float a0 = 0.f;
            #pragma unroll
            for (int d4 = 0; d4 < 16; d4++) {
                float4 qv = q4[d4], x = p0[d4];
                a0 += qv.x*x.x + qv.y*x.y + qv.z*x.z + qv.w*x.w;
            }
            Rs[qq * 132 + 128] = a0;
        }
    }
    __syncthreads();
    for (int idx = tid; idx < NREL * 64; idx += 256)
        PVt[(idx >> 6) * 68 + (idx & 63)] = posv[idx];

    float O[8][4];
    #pragma unroll
    for (int nf = 0; nf < 8; nf++)
        #pragma unroll
        for (int c = 0; c < 4; c++) O[nf][c] = 0.f;

    uint32_t a_off = (uint32_t)((wq * 16 + (lid & 15)) * FP) + ((lid >> 4) * 8) * 2;
    uint32_t bk_row = wk * 32 + ((lid >> 4) * 8) + (lid & 7);
    uint32_t bk_koff = ((lid >> 3) & 1) * 8;

    for (int kt = 0; kt < 24; kt++) {
        __syncthreads();
        #pragma unroll
        for (int p = 0; p < 2; p++) {
            int slot = tid + p * 256;
            int r = slot >> 3, i8 = slot & 7;
            int kg = kt * 64 + r;
            uint4 kh4 = make_uint4(0,0,0,0), kl4 = kh4;
            if (kg < CS) {
                kh4 = ((const uint4*)(g_kh + ho + (size_t)kg * CDH))[i8];
                kl4 = ((const uint4*)(g_kl + ho + (size_t)kg * CDH))[i8];
            }
            *(uint4*)(sm + OKH + r * FP + i8 * 16) = kh4;
            *(uint4*)(sm + OKL + r * FP + i8 * 16) = kl4;
            *(uint4*)(sm + OVH + r * FP + i8 * 16) = ((const uint4*)(g_vh + hv + (size_t)r * SPAD + kt * 64))[i8];
            *(uint4*)(sm + OVL + r * FP + i8 * 16) = ((const uint4*)(g_vl + hv + (size_t)r * SPAD + kt * 64))[i8];
        }
        __syncthreads();

        // S = QK^T (3-term split)
        float S[4][4];
        #pragma unroll
        for (int nf = 0; nf < 4; nf++)
            #pragma unroll
            for (int c = 0; c < 4; c++) S[nf][c] = 0.f;
        #pragma unroll
        for (int ks = 0; ks < 4; ks++) {
            uint32_t Ah[4], Al[4];
            ldsm4(Ah, sb + OQH + a_off + ks * 32);
            ldsm4(Al, sb + OQL + a_off + ks * 32);
            #pragma unroll
            for (int j2 = 0; j2 < 2; j2++) {
                uint32_t off = (bk_row + j2 * 16) * FP + (ks * 16 + bk_koff) * 2;
                uint32_t th[4], tl[4];
                ldsm4(th, sb + OKH + off);
                ldsm4(tl, sb + OKL + off);
                uint32_t B0h[2]={th[0],th[1]}, B1h[2]={th[2],th[3]};
                uint32_t B0l[2]={tl[0],tl[1]}, B1l[2]={tl[2],tl[3]};
                mma16816(S[j2*2], Ah, B0h); mma16816(S[j2*2], Ah, B0l); mma16816(S[j2*2], Al, B0h);
                mma16816(S[j2*2+1], Ah, B1h); mma16816(S[j2*2+1], Ah, B1l); mma16816(S[j2*2+1], Al, B1h);
            }
        }
        // bias + scale + mask + max
        float m0v = -1e30f, m1v = -1e30f;
        #pragma unroll
        for (int nf = 0; nf < 4; nf++) {
            int colb = wk * 32 + nf * 8 + qc;
            int kg0 = kt * 64 + colb, kg1 = kg0 + 1;
            int j00 = min(max(kg0-qg0,-64),64)+64, j01 = min(max(kg1-qg0,-64),64)+64;
            int j10 = min(max(kg0-qg1,-64),64)+64, j11 = min(max(kg1-qg1,-64),64)+64;
            float s0 = (S[nf][0] + Rs[row0*132+j00]) * 0.125f;
            float s1 = (S[nf][1] + Rs[row0*132+j01]) * 0.125f;
            float s2 = (S[nf][2] + Rs[row1*132+j10]) * 0.125f;
            float s3 = (S[nf][3] + Rs[row1*132+j11]) * 0.125f;
            if (kg0 >= CS) { s0 = -1e30f; s2 = -1e30f; }
            if (kg1 >= CS) { s1 = -1e30f; s3 = -1e30f; }
            S[nf][0]=s0; S[nf][1]=s1; S[nf][2]=s2; S[nf][3]=s3;
            m0v = fmaxf(m0v, fmaxf(s0, s1));
            m1v = fmaxf(m1v, fmaxf(s2, s3));
        }
        m0v = fmaxf(m0v, __shfl_xor_sync(~0u, m0v, 1)); m0v = fmaxf(m0v, __shfl_xor_sync(~0u, m0v, 2));
        m1v = fmaxf(m1v, __shfl_xor_sync(~0u, m1v, 1)); m1v = fmaxf(m1v, __shfl_xor_sync(~0u, m1v, 2));
        if ((lid & 3) == 0) { pmax[wk*64+row0] = m0v; pmax[wk*64+row1] = m1v; }
        __syncthreads();
        if (tid < 64) {
            float mo = row_m[tid];
            float mn = fmaxf(mo, fmaxf(pmax[tid], pmax[64 + tid]));
            ral[tid] = fexp(mo - mn);
            row_m[tid] = mn;
        }
        __syncthreads();

        int diff = kt * 64 - q0;
        bool band = (diff >= -64 && diff <= 64);
        float mr0 = row_m[row0], mr1 = row_m[row1];
        float s0a=0,s1a=0,l0a=0,l1a=0,h0a=0,h1a=0;
        uint32_t PhA[2][4], PlA[2][4];
        #pragma unroll
        for (int nf = 0; nf < 4; nf++) {
            int colb = wk * 32 + nf * 8 + qc;
            int kg = kt * 64 + colb;
            float p00 = fexp(S[nf][0]-mr0), p01 = fexp(S[nf][1]-mr0);
            float p10 = fexp(S[nf][2]-mr1), p11 = fexp(S[nf][3]-mr1);
            s0a += p00 + p01; s1a += p10 + p11;
            int e0 = kg - qg0, e1 = kg - qg1;
            l0a += (e0<=-64?p00:0.f) + (e0+1<=-64?p01:0.f);
            h0a += (e0>= 64?p00:0.f) + (e0+1>= 64?p01:0.f);
            l1a += (e1<=-64?p10:0.f) + (e1+1<=-64?p11:0.f);
            h1a += (e1>= 64?p10:0.f) + (e1+1>= 64?p11:0.f);
            float f00 = __bfloat162float(__float2bfloat16(p00));
            float f01 = __bfloat162float(__float2bfloat16(p01));
            float f10 = __bfloat162float(__float2bfloat16(p10));
            float f11 = __bfloat162float(__float2bfloat16(p11));
            int kc = nf >> 1, hx = (nf & 1) * 2;
            PhA[kc][hx]   = packbf(f00, f01);
            PhA[kc][hx+1] = packbf(f10, f11);
            PlA[kc][hx]   = packbf(p00 - f00, p01 - f01);
            PlA[kc][hx+1] = packbf(p10 - f10, p11 - f11);
            if (band) {
                *(float2*)&Pb[row0*68+colb] = make_float2(p00, p01);
                *(float2*)&Pb[row1*68+colb] = make_float2(p10, p11);
            }
        }
        float a0 = ral[row0], a1 = ral[row1];
        #pragma unroll
        for (int nf = 0; nf < 8; nf++) { O[nf][0]*=a0; O[nf][1]*=a0; O[nf][2]*=a1; O[nf][3]*=a1; }
        s0a += __shfl_xor_sync(~0u,s0a,1); s0a += __shfl_xor_sync(~0u,s0a,2);
        s1a += __shfl_xor_sync(~0u,s1a,1); s1a += __shfl_xor_sync(~0u,s1a,2);
        l0a += __shfl_xor_sync(~0u,l0a,1); l0a += __shfl_xor_sync(~0u,l0a,2);
        l1a += __shfl_xor_sync(~0u,l1a,1); l1a += __shfl_xor_sync(~0u,l1a,2);
        h0a += __shfl_xor_sync(~0u,h0a,1); h0a += __shfl_xor_sync(~0u,h0a,2);
        h1a += __shfl_xor_sync(~0u,h1a,1); h1a += __shfl_xor_sync(~0u,h1a,2);
        if ((lid & 3) == 0) {
            psm[wk*64+row0]=s0a; psm[wk*64+row1]=s1a;
            plo[wk*64+row0]=l0a; plo[wk*64+row1]=l1a;
            phi[wk*64+row0]=h0a; phi[wk*64+row1]=h1a;
        }
        __syncthreads();
        if (tid < 64) {
            float a = ral[tid];
            row_l[tid] = row_l[tid]*a + psm[tid] + psm[64+tid];
            rPL[tid]   = rPL[tid]*a + plo[tid] + plo[64+tid];
            rPH[tid]   = rPH[tid]*a + phi[tid] + phi[64+tid];
        }
        // PV (split): O += P @ V over warp's 32-k half
        #pragma unroll
        for (int kc = 0; kc < 2; kc++) {
            #pragma unroll
            for (int jd = 0; jd < 4; jd++) {
                uint32_t off = (jd*16 + ((lid>>4)*8) + (lid&7)) * FP
                             + (wk*32 + kc*16 + ((lid>>3)&1)*8) * 2;
                uint32_t th[4], tl[4];
                ldsm4(th, sb + OVH + off);
                ldsm4(tl, sb + OVL + off);
                uint32_t B0h[2]={th[0],th[1]}, B1h[2]={th[2],th[3]};
                uint32_t B0l[2]={tl[0],tl[1]}, B1l[2]={tl[2],tl[3]};
                mma16816(O[jd*2], PhA[kc], B0h); mma16816(O[jd*2], PhA[kc], B0l);
                mma16816(O[jd*2], PlA[kc], B0h);
                mma16816(O[jd*2+1], PhA[kc], B1h); mma16816(O[jd*2+1], PhA[kc], B1l);
                mma16816(O[jd*2+1], PlA[kc], B1h);
            }
        }
        // banded pos_v term
        if (band) {
            for (int k = wk*32; k < wk*32+32; k++) {
                int kg = kt * 64 + k;
                float p0 = Pb[row0*68+k], p1 = Pb[row1*68+k];
                int d0 = kg - qg0, d1 = kg - qg1;
                bool b0 = d0 > -64 && d0 < 64, b1 = d1 > -64 && d1 < 64;
                const float* r0p = PVt + (d0 + 64) * 68;
                const float* r1p = PVt + (d1 + 64) * 68;
                #pragma unroll
                for (int nf = 0; nf < 8; nf++) {
                    int col = nf * 8 + qc;
                    if (b0) { float2 v = *(const float2*)(r0p + col); O[nf][0] += p0*v.x; O[nf][1] += p0*v.y; }
                    if (b1) { float2 v = *(const float2*)(r1p + col); O[nf][2] += p1*v.x; O[nf][3] += p1*v.y; }
                }
            }
        }
    }

    // ---- epilogue: reduce halves, clip-mass terms, normalize, write bf16 hi/lo ----
    __syncthreads();
    if (wk == 0) {
        #pragma unroll
        for (int nf = 0; nf < 8; nf++) {
            int col = nf * 8 + qc;
            *(float2*)&Pb[row0*68+col] = make_float2(O[nf][0], O[nf][1]);
            *(float2*)&Pb[row1*68+col] = make_float2(O[nf][2], O[nf][3]);
        }
    }
    __syncthreads();
    if (wk == 1) {
        float il0 = 1.f / row_l[row0], il1 = 1.f / row_l[row1];
        float pl0 = rPL[row0], ph0 = rPH[row0], pl1 = rPL[row1], ph1 = rPH[row1];
        size_t ob0 = ((size_t)(bb * CS + qg0)) * CHID + hn * 64;
        size_t ob1 = ((size_t)(bb * CS + qg1)) * CHID + hn * 64;
        #pragma unroll
        for (int nf = 0; nf < 8; nf++) {
            int col = nf * 8 + qc;
            float2 v0 = *(float2*)&PVt[col];
            float2 v2 = *(float2*)&PVt[128*68+col];
            float2 w0 = *(float2*)&Pb[row0*68+col];
            float2 w1 = *(float2*)&Pb[row1*68+col];
            float o00 = (O[nf][0] + w0.x + pl0*v0.x + ph0*v2.x) * il0;
            float o01 = (O[nf][1] + w0.y + pl0*v0.y + ph0*v2.y) * il0;
            float o10 = (O[nf][2] + w1.x + pl1*v0.x + ph1*v2.x) * il1;
            float o11 = (O[nf][3] + w1.y + pl1*v0.y + ph1*v2.y) * il1;
            if (qg0 < CS) {
                __nv_bfloat16 hx = __float2bfloat16(o00), hy = __float2bfloat16(o01);
                *(__nv_bfloat162*)(g_xh + ob0 + col) = __halves2bfloat162(hx, hy);
                *(__nv_bfloat162*)(g_xl + ob0 + col) = __halves2bfloat162(
                    __float2bfloat16(o00 - __bfloat162float(hx)),
                    __float2bfloat16(o01 - __bfloat162float(hy)));
            }
            if (qg1 < CS) {
                __nv_bfloat16 hx = __float2bfloat16(o10), hy = __float2bfloat16(o11);
                *(__nv_bfloat162*)(g_xh + ob1 + col) = __halves2bfloat162(hx, hy);
                *(__nv_bfloat162*)(g_xl + ob1 + col) = __halves2bfloat162(
                    __float2bfloat16(o10 - __bfloat162float(hx)),
                    __float2bfloat16(o11 - __bfloat162float(hy)));
            }
        }
    }
}

// ============================================================================
extern "C" void kernel_launch(void* const* d_in, const int* in_sizes, int n_in,
                              void* d_out, int out_size)
{
    const float* query = (const float*)d_in[0];
    const float* key   = (const float*)d_in[1];
    const float* value = (const float*)d_in[2];
    const float* Wq    = (const float*)d_in[3];
    const float* bq    = (const float*)d_in[4];
    const float* Wk    = (const float*)d_in[5];
    const float* bk    = (const float*)d_in[6];
    const float* Wv    = (const float*)d_in[7];
    const float* bv    = (const float*)d_in[8];
    const float* posk  = (const float*)d_in[9];
    const float* posv  = (const float*)d_in[10];
    const float* Wfc   = (const float*)d_in[11];
    const float* bfc   = (const float*)d_in[12];
    float* out = (float*)d_out;

    __nv_bfloat16 *xh, *xl, *wh, *wl, *qh, *ql, *kh, *kl, *vh, *vl;
    cudaGetSymbolAddress((void**)&xh, g_xh);
    cudaGetSymbolAddress((void**)&xl, g_xl);
    cudaGetSymbolAddress((void**)&wh, g_wh);
    cudaGetSymbolAddress((void**)&wl, g_wl);
    cudaGetSymbolAddress((void**)&qh, g_qh);
    cudaGetSymbolAddress((void**)&ql, g_ql);
    cudaGetSymbolAddress((void**)&kh, g_kh);
    cudaGetSymbolAddress((void**)&kl, g_kl);
    cudaGetSymbolAddress((void**)&vh, g_vh);
    cudaGetSymbolAddress((void**)&vl, g_vl);

    cudaFuncSetAttribute(gemm_mma<0>, cudaFuncAttributeMaxDynamicSharedMemorySize, GEMM_SMEM_BYTES);
    cudaFuncSetAttribute(gemm_mma<2>, cudaFuncAttributeMaxDynamicSharedMemorySize, GEMM_SMEM_BYTES);
    cudaFuncSetAttribute(gemm_mma<3>, cudaFuncAttributeMaxDynamicSharedMemorySize, GEMM_SMEM_BYTES);
    cudaFuncSetAttribute(flash_mma, cudaFuncAttributeMaxDynamicSharedMemorySize, FSM);

    const int nX = MROWS * CHID, nW = CHID * CHID;
    dim3 ggrid((MROWS + 127) / 128, CHID / 128);

    cvt_split<<<(nX + 255) / 256, 256>>>(query, xh, xl, nX);
    cvt_w_proj<<<(nW + 255) / 256, 256>>>(Wq, wh, wl);
    gemm_mma<0><<<ggrid, 256, GEMM_SMEM_BYTES>>>(xh, xl, wh, wl, bq, nullptr, qh, ql);

    cvt_split<<<(nX + 255) / 256, 256>>>(key, xh, xl, nX);
    cvt_w_proj<<<(nW + 255) / 256, 256>>>(Wk, wh, wl);
    gemm_mma<0><<<ggrid, 256, GEMM_SMEM_BYTES>>>(xh, xl, wh, wl, bk, nullptr, kh, kl);

    cvt_split<<<(nX + 255) / 256, 256>>>(value, xh, xl, nX);
    cvt_w_proj<<<(nW + 255) / 256, 256>>>(Wv, wh, wl);
    gemm_mma<2><<<ggrid, 256, GEMM_SMEM_BYTES>>>(xh, xl, wh, wl, bv, nullptr, vh, vl);

    flash_mma<<<dim3(24, CNH, CB), 256, FSM>>>(posk, posv);

    cvt_w_fc<<<(nW + 255) / 256, 256>>>(Wfc, wh, wl);
    gemm_mma<3><<<ggrid, 256, GEMM_SMEM_BYTES>>>(xh, xl, wh, wl, bfc, out, nullptr, nullptr);
}

// round 14
// speedup vs baseline: 1.6725x; 1.0352x over previous
#include <cuda_runtime.h>
#include <cuda_bf16.h>
#include <stdint.h>

#define CB 4
#define CS 1500
#define CHID 1024
#define CNH 16
#define CDH 64
#define NREL 129
#define MROWS (CB*CS)      // 6000
#define SPAD 1536          // padded S for V^T rows

// ---------------- scratch (device globals; zero-initialized) ----------------
__device__ __align__(16) __nv_bfloat16 g_qh[CB*CNH*CS*CDH];
__device__ __align__(16) __nv_bfloat16 g_ql[CB*CNH*CS*CDH];
__device__ __align__(16) __nv_bfloat16 g_kh[CB*CNH*CS*CDH];
__device__ __align__(16) __nv_bfloat16 g_kl[CB*CNH*CS*CDH];
__device__ __align__(16) __nv_bfloat16 g_vh[CB*CNH*CDH*SPAD];  // V^T [B,NH,DH,SPAD]
__device__ __align__(16) __nv_bfloat16 g_vl[CB*CNH*CDH*SPAD];
__device__ __align__(16) __nv_bfloat16 g_xh[MROWS*CHID];       // GEMM A / hidden
__device__ __align__(16) __nv_bfloat16 g_xl[MROWS*CHID];
__device__ __align__(16) __nv_bfloat16 g_wh[CHID*CHID];
__device__ __align__(16) __nv_bfloat16 g_wl[CHID*CHID];

// ---------------- helpers ----------------
__device__ __forceinline__ uint32_t smem_u32(const void* p) {
    uint32_t a;
    asm("{ .reg .u64 t; cvta.to.shared.u64 t, %1; cvt.u32.u64 %0, t; }" : "=r"(a) : "l"(p));
    return a;
}
__device__ __forceinline__ void ldsm4(uint32_t* r, uint32_t a) {
    asm volatile("ldmatrix.sync.aligned.m8n8.x4.shared.b16 {%0,%1,%2,%3}, [%4];"
                 : "=r"(r[0]), "=r"(r[1]), "=r"(r[2]), "=r"(r[3]) : "r"(a));
}
__device__ __forceinline__ void mma16816(float* c, const uint32_t* a, const uint32_t* b) {
    asm volatile(
        "mma.sync.aligned.m16n8k16.row.col.f32.bf16.bf16.f32 "
        "{%0,%1,%2,%3}, {%4,%5,%6,%7}, {%8,%9}, {%0,%1,%2,%3};"
        : "+f"(c[0]), "+f"(c[1]), "+f"(c[2]), "+f"(c[3])
        : "r"(a[0]), "r"(a[1]), "r"(a[2]), "r"(a[3]), "r"(b[0]), "r"(b[1]));
}
__device__ __forceinline__ void cpa16(uint32_t dst, const void* src, int sz) {
    asm volatile("cp.async.cg.shared.global [%0], [%1], 16, %2;"
                 :: "r"(dst), "l"(src), "r"(sz) : "memory");
}
#define CPA_COMMIT() asm volatile("cp.async.commit_group;" ::: "memory")
#define CPA_WAIT0()  asm volatile("cp.async.wait_group 0;" ::: "memory")
// FFMA-only exp (no MUFU). valid for x <= 0, clamped at 2^-120.
__device__ __forceinline__ float fexp(float x) {
    float y = fmaxf(x * 1.4426950408889634f, -120.0f);
    float z = y + 12582912.0f;
    int   i = __float_as_int(z) - 0x4B400000;
    float f = y - (z - 12582912.0f);
    float p =      1.3333558146e-3f;
    p = fmaf(p, f, 9.6181291076e-3f);
    p = fmaf(p, f, 5.5504108665e-2f);
    p = fmaf(p, f, 2.4022650696e-1f);
    p = fmaf(p, f, 6.9314718056e-1f);
    p = fmaf(p, f, 1.0f);
    return __int_as_float(__float_as_int(p) + (i << 23));
}
__device__ __forceinline__ uint32_t packbf(float a, float b) {
    __nv_bfloat162 t = __halves2bfloat162(__float2bfloat16(a), __float2bfloat16(b));
    return *(uint32_t*)&t;
}

// ---------------- conversion kernels ----------------
__global__ void cvt_split(const float* __restrict__ x,
                          __nv_bfloat16* __restrict__ hi, __nv_bfloat16* __restrict__ lo, int n) {
    int i = blockIdx.x * blockDim.x + threadIdx.x;
    if (i < n) {
        float v = x[i];
        __nv_bfloat16 h = __float2bfloat16(v);
        hi[i] = h; lo[i] = __float2bfloat16(v - __bfloat162float(h));
    }
}
__global__ void cvt_w_proj(const float* __restrict__ W,
                           __nv_bfloat16* __restrict__ hi, __nv_bfloat16* __restrict__ lo) {
    int i = blockIdx.x * blockDim.x + threadIdx.x;
    if (i < CHID * CHID) {
        int col = i >> 10, k = i & 1023;
        float v = W[((size_t)(col >> 6) * CHID + k) * CDH + (col & 63)];
        __nv_bfloat16 h = __float2bfloat16(v);
        hi[i] = h; lo[i] = __float2bfloat16(v - __bfloat162float(h));
    }
}
__global__ void cvt_w_fc(const float* __restrict__ W,
                         __nv_bfloat16* __restrict__ hi, __nv_bfloat16* __restrict__ lo) {
    int i = blockIdx.x * blockDim.x + threadIdx.x;
    if (i < CHID * CHID) {
        int col = i >> 10, k = i & 1023;
        float v = W[(size_t)k * CHID + col];
        __nv_bfloat16 h = __float2bfloat16(v);
        hi[i] = h; lo[i] = __float2bfloat16(v - __bfloat162float(h));
    }
}

// ============================================================================
// mma.sync split-bf16 GEMM (R7/R13-validated core, unchanged).
// MODE 0: bf16 hi/lo scatter [B,NH,S,DH]; MODE 2: bf16 hi/lo V^T; MODE 3: fp32
// ============================================================================
#define SPITCH 144
#define TILE_BYTES (128 * SPITCH)
#define GEMM_SMEM_BYTES (4 * TILE_BYTES)

template<int MODE>
__global__ __launch_bounds__(256, 1) void gemm_mma(
    const __nv_bfloat16* __restrict__ Xh, const __nv_bfloat16* __restrict__ Xl,
    const __nv_bfloat16* __restrict__ Wh, const __nv_bfloat16* __restrict__ Wl,
    const float* __restrict__ bias, float* __restrict__ outf,
    __nv_bfloat16* __restrict__ oh, __nv_bfloat16* __restrict__ ol)
{
    extern __shared__ char smem[];
    uint32_t sbase = smem_u32(smem);
    int tid = threadIdx.x, wid = tid >> 5, lid = tid & 31;
    int wm = wid & 1, wn = wid >> 1;
    int m0 = blockIdx.x * 128, n0 = blockIdx.y * 128;

    float C[4][4][4];
    #pragma unroll
    for (int i = 0; i < 4; i++)
        #pragma unroll
        for (int j = 0; j < 4; j++)
            #pragma unroll
            for (int r = 0; r < 4; r++) C[i][j][r] = 0.f;

    uint32_t a_row = wm * 64 + (lid & 15), a_koff = (lid >> 4) * 8;
    uint32_t b_n = wn * 32 + ((lid >> 4) * 8) + (lid & 7);
    uint32_t b_koff = ((lid >> 3) & 1) * 8;

    for (int c = 0; c < CHID / 64; c++) {
        __syncthreads();
        #pragma unroll
        for (int t = 0; t < 4; t++) {
            const __nv_bfloat16* src = (t == 0) ? Xh : (t == 1) ? Xl : (t == 2) ? Wh : Wl;
            const bool isA = (t < 2);
            char* db = smem + t * TILE_BYTES;
            #pragma unroll
            for (int p = 0; p < 4; p++) {
                int slot = tid + p * 256;
                int row = slot >> 3, i8 = slot & 7;
                int gr = (isA ? m0 : n0) + row;
                uint4 v = make_uint4(0, 0, 0, 0);
                if (!isA || gr < MROWS)
                    v = ((const uint4*)(src + (size_t)gr * CHID + c * 64))[i8];
                *(uint4*)(db + row * SPITCH + i8 * 16) = v;
            }
        }
        __syncthreads();
        #pragma unroll
        for (int ks = 0; ks < 4; ks++) {
            uint32_t Ah[4][4], Al[4][4], Bh[4][2], Bl[4][2];
            #pragma unroll
            for (int i = 0; i < 4; i++) {
                uint32_t off = (a_row + i * 16) * SPITCH + (ks * 16 + a_koff) * 2;
                ldsm4(Ah[i], sbase + 0 * TILE_BYTES + off);
                ldsm4(Al[i], sbase + 1 * TILE_BYTES + off);
            }
            #pragma unroll
            for (int j2 = 0; j2 < 2; j2++) {
                uint32_t off = (b_n + j2 * 16) * SPITCH + (ks * 16 + b_koff) * 2;
                uint32_t tmp[4];
                ldsm4(tmp, sbase + 2 * TILE_BYTES + off);
                Bh[j2*2][0] = tmp[0]; Bh[j2*2][1] = tmp[1];
                Bh[j2*2+1][0] = tmp[2]; Bh[j2*2+1][1] = tmp[3];
                ldsm4(tmp, sbase + 3 * TILE_BYTES + off);
                Bl[j2*2][0] = tmp[0]; Bl[j2*2][1] = tmp[1];
                Bl[j2*2+1][0] = tmp[2]; Bl[j2*2+1][1] = tmp[3];
            }
            #pragma unroll
            for (int i = 0; i < 4; i++)
                #pragma unroll
                for (int j = 0; j < 4; j++) {
                    mma16816(C[i][j], Ah[i], Bh[j]);
                    mma16816(C[i][j], Ah[i], Bl[j]);
                    mma16816(C[i][j], Al[i], Bh[j]);
                }
        }
    }
    int r = lid >> 2, cg = (lid & 3) * 2;
    #pragma unroll
    for (int i = 0; i < 4; i++) {
        int rows[2] = { m0 + wm*64 + i*16 + r, m0 + wm*64 + i*16 + r + 8 };
        #pragma unroll
        for (int j = 0; j < 4; j++) {
            int col = n0 + wn * 32 + j * 8 + cg;
            float b0 = bias[col], b1 = bias[col + 1];
            float vx[2] = { C[i][j][0] + b0, C[i][j][2] + b0 };
            float vy[2] = { C[i][j][1] + b1, C[i][j][3] + b1 };
            #pragma unroll
            for (int h = 0; h < 2; h++) {
                int row = rows[h];
                if (row >= MROWS) continue;
                if (MODE == 3) {
                    *(float2*)(outf + (size_t)row * CHID + col) = make_float2(vx[h], vy[h]);
                } else {
                    int bi = row / CS, s = row - bi * CS;
                    int n = col >> 6, d = col & 63;
                    __nv_bfloat16 hx = __float2bfloat16(vx[h]), hy = __float2bfloat16(vy[h]);
                    __nv_bfloat16 lx = __float2bfloat16(vx[h] - __bfloat162float(hx));
                    __nv_bfloat16 ly = __float2bfloat16(vy[h] - __bfloat162float(hy));
                    if (MODE == 0) {
                        size_t a = (((size_t)(bi * CNH + n)) * CS + s) * CDH + d;
                        *(__nv_bfloat162*)(oh + a) = __halves2bfloat162(hx, hy);
                        *(__nv_bfloat162*)(ol + a) = __halves2bfloat162(lx, ly);
                    } else {
                        size_t base = (size_t)(bi * CNH + n) * CDH;
                        oh[(base + d) * SPAD + s] = hx; oh[(base + d + 1) * SPAD + s] = hy;
                        ol[(base + d) * SPAD + s] = lx; ol[(base + d + 1) * SPAD + s] = ly;
                    }
                }
            }
        }
    }
}

// ============================================================================
// Tensor-core flash attention + Shaw bias.
// cp.async double-buffered K/V; softmax state replicated in registers;
// 3 syncthreads per k-tile. Block = (qtile64, head, batch), 8 warps.
// ============================================================================
#define FP 144
#define OQH 0
#define OQL 9216
#define OKB 18432               // K/V buffers: 2 x 36864 (KH,KL,VH,VL each 9216)
#define ORS 92160               // fp32 [64][132]
#define OPV 125952              // fp32 [129][68]
#define OPB 161040              // fp32 [64][68]
#define OEX 178448              // xmax/xsum/xlo/xhi: 4 x 128 floats
#define FSM 180496

__global__ __launch_bounds__(256, 1) void flash_mma(
    const float* __restrict__ posk, const float* __restrict__ posv)
{
    extern __shared__ char sm[];
    uint32_t sb = smem_u32(sm);
    float* Rs   = (float*)(sm + ORS);
    float* PVt  = (float*)(sm + OPV);
    float* Pb   = (float*)(sm + OPB);
    float* xmax = (float*)(sm + OEX);
    float* xsum = xmax + 128;
    float* xlo  = xmax + 256;
    float* xhi  = xmax + 384;

    int qt = blockIdx.x, hn = blockIdx.y, bb = blockIdx.z;
    int q0 = qt * 64;
    size_t ho = ((size_t)(bb * CNH + hn)) * CS * CDH;
    size_t hv = ((size_t)(bb * CNH + hn)) * CDH * SPAD;
    int tid = threadIdx.x, wid = tid >> 5, lid = tid & 31;
    int wq = wid & 3, wk = wid >> 2;
    int qr = lid >> 2, qc = (lid & 3) * 2;
    int row0 = wq * 16 + qr, row1 = row0 + 8;
    int qg0 = q0 + row0, qg1 = q0 + row1;

    // issue K/V loads for tile 0 (buffer 0) immediately
    auto issue_kv = [&](int kt2, uint32_t kb) {
        #pragma unroll
        for (int p = 0; p < 2; p++) {
            int slot = tid + p * 256;
            int r = slot >> 3, i8 = slot & 7;
            int kg = kt2 * 64 + r;
            int sz = (kg < CS) ? 16 : 0;
            int kgc = (kg < CS) ? kg : (CS - 1);
            cpa16(sb + kb + r * FP + i8 * 16,         g_kh + ho + (size_t)kgc * CDH + i8 * 8, sz);
            cpa16(sb + kb + 9216 + r * FP + i8 * 16,  g_kl + ho + (size_t)kgc * CDH + i8 * 8, sz);
            cpa16(sb + kb + 18432 + r * FP + i8 * 16, g_vh + hv + (size_t)r * SPAD + kt2 * 64 + i8 * 8, 16);
            cpa16(sb + kb + 27648 + r * FP + i8 * 16, g_vl + hv + (size_t)r * SPAD + kt2 * 64 + i8 * 8, 16);
        }
    };
    issue_kv(0, OKB);
    CPA_COMMIT();

    // ---- prologue: Q tiles, posk -> PVt, fp32 Q -> Pb, Rs table ----
    #pragma unroll
    for (int p = 0; p < 2; p++) {
        int slot = tid + p * 256;
        int r = slot >> 3, i8 = slot & 7;
        int qg = q0 + r;
        uint4 vh = make_uint4(0,0,0,0), vl = vh;
        if (qg < CS) {
            vh = ((const uint4*)(g_qh + ho + (size_t)qg * CDH))[i8];
            vl = ((const uint4*)(g_ql + ho + (size_t)qg * CDH))[i8];
        }
        *(uint4*)(sm + OQH + r * FP + i8 * 16) = vh;
        *(uint4*)(sm + OQL + r * FP + i8 * 16) = vl;
    }
    for (int idx = tid; idx < NREL * 64; idx += 256)
        PVt[(idx >> 6) * 68 + (idx & 63)] = posk[idx];
    __syncthreads();
    for (int idx = tid; idx < 64 * 64; idx += 256) {
        int r = idx >> 6, d = idx & 63;
        Pb[r * 68 + d] = __bfloat162float(*(__nv_bfloat16*)(sm + OQH + r * FP + d * 2))
                       + __bfloat162float(*(__nv_bfloat16*)(sm + OQL + r * FP + d * 2));
    }
    __syncthreads();
    for (int t = tid; t < 64 * 33; t += 256) {
        int qq = t / 33, jg = t - qq * 33, j0 = jg * 4;
        const float4* q4 = (const float4*)(Pb + qq * 68);
        if (jg < 32) {
            const float4 *p0 = (const float4*)(PVt + (j0+0)*68), *p1 = (const float4*)(PVt + (j0+1)*68);
            const float4 *p2 = (const float4*)(PVt + (j0+2)*68), *p3 = (const float4*)(PVt + (j0+3)*68);
            float a0=0,a1=0,a2=0,a3=0;
            #pragma unroll
            for (int d4 = 0; d4 < 16; d4++) {
                float4 qv = q4[d4]; float4 x;
                x=p0[d4]; a0+=qv.x*x.x+qv.y*x.y+qv.z*x.z+qv.w*x.w;
                x=p1[d4]; a1+=qv.x*x.x+qv.y*x.y+qv.z*x.z+qv.w*x.w;
                x=p2[d4]; a2+=qv.x*x.x+qv.y*x.y+qv.z*x.z+qv.w*x.w;
                x=p3[d4]; a3+=qv.x*x.x+qv.y*x.y+qv.z*x.z+qv.w*x.w;
            }
            Rs[qq*132+j0]=a0; Rs[qq*132+j0+1]=a1; Rs[qq*132+j0+2]=a2; Rs[qq*132+j0+3]=a3;
        } else {
            const float4* p0 = (const float4*)(PVt + 128 * 68);
            float a0 = 0.f;
            #pragma unroll
            for (int d4 = 0; d4 < 16; d4++) {
                float4 qv = q4[d4], x = p0[d4];
                a0 += qv.x*x.x + qv.y*x.y + qv.z*x.z + qv.w*x.w;
            }
            Rs[qq * 132 + 128] = a0;
        }
    }
    __syncthreads();
    for (int idx = tid; idx < NREL * 64; idx += 256)
        PVt[(idx >> 6) * 68 + (idx & 63)] = posv[idx];

    // replicated per-row softmax state (rows row0/row1)
    float rm0 = -1e30f, rm1 = -1e30f, rl0 = 0.f, rl1 = 0.f;
    float rL0 = 0.f, rL1 = 0.f, rH0 = 0.f, rH1 = 0.f;
    float O[8][4];
    #pragma unroll
    for (int nf = 0; nf < 8; nf++)
        #pragma unroll
        for (int c = 0; c < 4; c++) O[nf][c] = 0.f;

    uint32_t a_off = (uint32_t)((wq * 16 + (lid & 15)) * FP) + ((lid >> 4) * 8) * 2;
    uint32_t bk_row = wk * 32 + ((lid >> 4) * 8) + (lid & 7);
    uint32_t bk_koff = ((lid >> 3) & 1) * 8;
    uint32_t v_row = ((lid >> 4) * 8) + (lid & 7);

    for (int kt = 0; kt < 24; kt++) {
        uint32_t kb = OKB + (kt & 1) * 36864;
        CPA_WAIT0();
        __syncthreads();                                   // #1: tiles ready, exch free
        if (kt < 23) { issue_kv(kt + 1, OKB + ((kt + 1) & 1) * 36864); CPA_COMMIT(); }

        // ---- S = QK^T (3-term split) ----
        float S[4][4];
        #pragma unroll
        for (int nf = 0; nf < 4; nf++)
            #pragma unroll
            for (int c = 0; c < 4; c++) S[nf][c] = 0.f;
        #pragma unroll
        for (int ks = 0; ks < 4; ks++) {
            uint32_t Ah[4], Al[4];
            ldsm4(Ah, sb + OQH + a_off + ks * 32);
            ldsm4(Al, sb + OQL + a_off + ks * 32);
            #pragma unroll
            for (int j2 = 0; j2 < 2; j2++) {
                uint32_t off = (bk_row + j2 * 16) * FP + (ks * 16 + bk_koff) * 2;
                uint32_t th[4], tl[4];
                ldsm4(th, sb + kb + off);
                ldsm4(tl, sb + kb + 9216 + off);
                uint32_t B0h[2]={th[0],th[1]}, B1h[2]={th[2],th[3]};
                uint32_t B0l[2]={tl[0],tl[1]}, B1l[2]={tl[2],tl[3]};
                mma16816(S[j2*2], Ah, B0h); mma16816(S[j2*2], Ah, B0l); mma16816(S[j2*2], Al, B0h);
                mma16816(S[j2*2+1], Ah, B1h); mma16816(S[j2*2+1], Ah, B1l); mma16816(S[j2*2+1], Al, B1h);
            }
        }
        // ---- bias + scale + mask + partial max ----
        float m0v = -1e30f, m1v = -1e30f;
        #pragma unroll
        for (int nf = 0; nf < 4; nf++) {
            int colb = wk * 32 + nf * 8 + qc;
            int kg0 = kt * 64 + colb, kg1 = kg0 + 1;
            int j00 = min(max(kg0-qg0,-64),64)+64, j01 = min(max(kg1-qg0,-64),64)+64;
            int j10 = min(max(kg0-qg1,-64),64)+64, j11 = min(max(kg1-qg1,-64),64)+64;
            float s0 = (S[nf][0] + Rs[row0*132+j00]) * 0.125f;
            float s1 = (S[nf][1] + Rs[row0*132+j01]) * 0.125f;
            float s2 = (S[nf][2] + Rs[row1*132+j10]) * 0.125f;
            float s3 = (S[nf][3] + Rs[row1*132+j11]) * 0.125f;
            if (kg0 >= CS) { s0 = -1e30f; s2 = -1e30f; }
            if (kg1 >= CS) { s1 = -1e30f; s3 = -1e30f; }
            S[nf][0]=s0; S[nf][1]=s1; S[nf][2]=s2; S[nf][3]=s3;
            m0v = fmaxf(m0v, fmaxf(s0, s1));
            m1v = fmaxf(m1v, fmaxf(s2, s3));
        }
        m0v = fmaxf(m0v, __shfl_xor_sync(~0u, m0v, 1)); m0v = fmaxf(m0v, __shfl_xor_sync(~0u, m0v, 2));
        m1v = fmaxf(m1v, __shfl_xor_sync(~0u, m1v, 1)); m1v = fmaxf(m1v, __shfl_xor_sync(~0u, m1v, 2));
        if ((lid & 3) == 0) { xmax[wk*64+row0] = m0v; xmax[wk*64+row1] = m1v; }
        __syncthreads();                                   // #2: xmax ready

        // ---- replicated state update (all threads, no serialization) ----
        float mn0 = fmaxf(rm0, fmaxf(xmax[row0], xmax[64 + row0]));
        float mn1 = fmaxf(rm1, fmaxf(xmax[row1], xmax[64 + row1]));
        float al0 = fexp(rm0 - mn0), al1 = fexp(rm1 - mn1);
        rm0 = mn0; rm1 = mn1;
        #pragma unroll
        for (int nf = 0; nf < 8; nf++) { O[nf][0]*=al0; O[nf][1]*=al0; O[nf][2]*=al1; O[nf][3]*=al1; }

        int diff = kt * 64 - q0;
        bool band = (diff >= -64 && diff <= 64);
        float s0a=0,s1a=0,l0a=0,l1a=0,h0a=0,h1a=0;
        uint32_t PhA[2][4], PlA[2][4];
        #pragma unroll
        for (int nf = 0; nf < 4; nf++) {
            int colb = wk * 32 + nf * 8 + qc;
            int kg = kt * 64 + colb;
            float p00 = fexp(S[nf][0]-mn0), p01 = fexp(S[nf][1]-mn0);
            float p10 = fexp(S[nf][2]-mn1), p11 = fexp(S[nf][3]-mn1);
            s0a += p00 + p01; s1a += p10 + p11;
            int e0 = kg - qg0, e1 = kg - qg1;
            l0a += (e0<=-64?p00:0.f) + (e0+1<=-64?p01:0.f);
            h0a += (e0>= 64?p00:0.f) + (e0+1>= 64?p01:0.f);
            l1a += (e1<=-64?p10:0.f) + (e1+1<=-64?p11:0.f);
            h1a += (e1>= 64?p10:0.f) + (e1+1>= 64?p11:0.f);
            float f00 = __bfloat162float(__float2bfloat16(p00));
            float f01 = __bfloat162float(__float2bfloat16(p01));
            float f10 = __bfloat162float(__float2bfloat16(p10));
            float f11 = __bfloat162float(__float2bfloat16(p11));
            int kc = nf >> 1, hx = (nf & 1) * 2;
            PhA[kc][hx]   = packbf(f00, f01);
            PhA[kc][hx+1] = packbf(f10, f11);
            PlA[kc][hx]   = packbf(p00 - f00, p01 - f01);
            PlA[kc][hx+1] = packbf(p10 - f10, p11 - f11);
            if (band) {
                *(float2*)&Pb[row0*68+colb] = make_float2(p00, p01);
                *(float2*)&Pb[row1*68+colb] = make_float2(p10, p11);
            }
        }
        s0a += __shfl_xor_sync(~0u,s0a,1); s0a += __shfl_xor_sync(~0u,s0a,2);
        s1a += __shfl_xor_sync(~0u,s1a,1); s1a += __shfl_xor_sync(~0u,s1a,2);
        l0a += __shfl_xor_sync(~0u,l0a,1); l0a += __shfl_xor_sync(~0u,l0a,2);
        l1a += __shfl_xor_sync(~0u,l1a,1); l1a += __shfl_xor_sync(~0u,l1a,2);
        h0a += __shfl_xor_sync(~0u,h0a,1); h0a += __shfl_xor_sync(~0u,h0a,2);
        h1a += __shfl_xor_sync(~0u,h1a,1); h1a += __shfl_xor_sync(~0u,h1a,2);
        if ((lid & 3) == 0) {
            xsum[wk*64+row0]=s0a; xsum[wk*64+row1]=s1a;
            xlo[wk*64+row0]=l0a;  xlo[wk*64+row1]=l1a;
            xhi[wk*64+row0]=h0a;  xhi[wk*64+row1]=h1a;
        }
        __syncwarp();       // Pb band staging is intra-warp

        // ---- O += P @ V over warp's 32-k half (3-term split) ----
        #pragma unroll
        for (int kc = 0; kc < 2; kc++) {
            #pragma unroll
            for (int jd = 0; jd < 4; jd++) {
                uint32_t off = (jd*16 + v_row) * FP + (wk*32 + kc*16 + ((lid>>3)&1)*8) * 2;
                uint32_t th[4], tl[4];
                ldsm4(th, sb + kb + 18432 + off);
                ldsm4(tl, sb + kb + 27648 + off);
                uint32_t B0h[2]={th[0],th[1]}, B1h[2]={th[2],th[3]};
                uint32_t B0l[2]={tl[0],tl[1]}, B1l[2]={tl[2],tl[3]};
                mma16816(O[jd*2], PhA[kc], B0h); mma16816(O[jd*2], PhA[kc], B0l);
                mma16816(O[jd*2], PlA[kc], B0h);
                mma16816(O[jd*2+1], PhA[kc], B1h); mma16816(O[jd*2+1], PhA[kc], B1l);
                mma16816(O[jd*2+1], PlA[kc], B1h);
            }
        }
        // ---- banded pos_v term (3 of 24 tiles) ----
        if (band) {
            for (int k = wk*32; k < wk*32+32; k++) {
                int kg = kt * 64 + k;
                float p0 = Pb[row0*68+k], p1 = Pb[row1*68+k];
                int d0 = kg - qg0, d1 = kg - qg1;
                bool b0 = d0 > -64 && d0 < 64, b1 = d1 > -64 && d1 < 64;
                const float* r0p = PVt + (d0 + 64) * 68;
                const float* r1p = PVt + (d1 + 64) * 68;
                #pragma unroll
                for (int nf = 0; nf < 8; nf++) {
                    int col = nf * 8 + qc;
                    if (b0) { float2 v = *(const float2*)(r0p + col); O[nf][0] += p0*v.x; O[nf][1] += p0*v.y; }
                    if (b1) { float2 v = *(const float2*)(r1p + col); O[nf][2] += p1*v.x; O[nf][3] += p1*v.y; }
                }
            }
        }
        __syncthreads();                                   // #3: xsum/xlo/xhi ready
        rl0 = rl0*al0 + xsum[row0] + xsum[64+row0];
        rl1 = rl1*al1 + xsum[row1] + xsum[64+row1];
        rL0 = rL0*al0 + xlo[row0]  + xlo[64+row0];
        rL1 = rL1*al1 + xlo[row1]  + xlo[64+row1];
        rH0 = rH0*al0 + xhi[row0]  + xhi[64+row0];
        rH1 = rH1*al1 + xhi[row1]  + xhi[64+row1];
    }

    // ---- epilogue: reduce halves, clip-mass terms, normalize, write bf16 hi/lo ----
    __syncthreads();
    if (wk == 0) {
        #pragma unroll
        for (int nf = 0; nf < 8; nf++) {
            int col = nf * 8 + qc;
            *(float2*)&Pb[row0*68+col] = make_float2(O[nf][0], O[nf][1]);
            *(float2*)&Pb[row1*68+col] = make_float2(O[nf][2], O[nf][3]);
        }
    }
    __syncthreads();
    if (wk == 1) {
        float il0 = 1.f / rl0, il1 = 1.f / rl1;
        size_t ob0 = ((size_t)(bb * CS + qg0)) * CHID + hn * 64;
        size_t ob1 = ((size_t)(bb * CS + qg1)) * CHID + hn * 64;
        #pragma unroll
        for (int nf = 0; nf < 8; nf++) {
            int col = nf * 8 + qc;
            float2 v0 = *(float2*)&PVt[col];
            float2 v2 = *(float2*)&PVt[128*68+col];
            float2 w0 = *(float2*)&Pb[row0*68+col];
            float2 w1 = *(float2*)&Pb[row1*68+col];
            float o00 = (O[nf][0] + w0.x + rL0*v0.x + rH0*v2.x) * il0;
            float o01 = (O[nf][1] + w0.y + rL0*v0.y + rH0*v2.y) * il0;
            float o10 = (O[nf][2] + w1.x + rL1*v0.x + rH1*v2.x) * il1;
            float o11 = (O[nf][3] + w1.y + rL1*v0.y + rH1*v2.y) * il1;
            if (qg0 < CS) {
                __nv_bfloat16 hx = __float2bfloat16(o00), hy = __float2bfloat16(o01);
                *(__nv_bfloat162*)(g_xh + ob0 + col) = __halves2bfloat162(hx, hy);
                *(__nv_bfloat162*)(g_xl + ob0 + col) = __halves2bfloat162(
                    __float2bfloat16(o00 - __bfloat162float(hx)),
                    __float2bfloat16(o01 - __bfloat162float(hy)));
            }
            if (qg1 < CS) {
                __nv_bfloat16 hx = __float2bfloat16(o10), hy = __float2bfloat16(o11);
                *(__nv_bfloat162*)(g_xh + ob1 + col) = __halves2bfloat162(hx, hy);
                *(__nv_bfloat162*)(g_xl + ob1 + col) = __halves2bfloat162(
                    __float2bfloat16(o10 - __bfloat162float(hx)),
                    __float2bfloat16(o11 - __bfloat162float(hy)));
            }
        }
    }
}

// ============================================================================
extern "C" void kernel_launch(void* const* d_in, const int* in_sizes, int n_in,
                              void* d_out, int out_size)
{
    const float* query = (const float*)d_in[0];
    const float* key   = (const float*)d_in[1];
    const float* value = (const float*)d_in[2];
    const float* Wq    = (const float*)d_in[3];
    const float* bq    = (const float*)d_in[4];
    const float* Wk    = (const float*)d_in[5];
    const float* bk    = (const float*)d_in[6];
    const float* Wv    = (const float*)d_in[7];
    const float* bv    = (const float*)d_in[8];
    const float* posk  = (const float*)d_in[9];
    const float* posv  = (const float*)d_in[10];
    const float* Wfc   = (const float*)d_in[11];
    const float* bfc   = (const float*)d_in[12];
    float* out = (float*)d_out;

    __nv_bfloat16 *xh, *xl, *wh, *wl, *qh, *ql, *kh, *kl, *vh, *vl;
    cudaGetSymbolAddress((void**)&xh, g_xh);
    cudaGetSymbolAddress((void**)&xl, g_xl);
    cudaGetSymbolAddress((void**)&wh, g_wh);
    cudaGetSymbolAddress((void**)&wl, g_wl);
    cudaGetSymbolAddress((void**)&qh, g_qh);
    cudaGetSymbolAddress((void**)&ql, g_ql);
    cudaGetSymbolAddress((void**)&kh, g_kh);
    cudaGetSymbolAddress((void**)&kl, g_kl);
    cudaGetSymbolAddress((void**)&vh, g_vh);
    cudaGetSymbolAddress((void**)&vl, g_vl);

    cudaFuncSetAttribute(gemm_mma<0>, cudaFuncAttributeMaxDynamicSharedMemorySize, GEMM_SMEM_BYTES);
    cudaFuncSetAttribute(gemm_mma<2>, cudaFuncAttributeMaxDynamicSharedMemorySize, GEMM_SMEM_BYTES);
    cudaFuncSetAttribute(gemm_mma<3>, cudaFuncAttributeMaxDynamicSharedMemorySize, GEMM_SMEM_BYTES);
    cudaFuncSetAttribute(flash_mma, cudaFuncAttributeMaxDynamicSharedMemorySize, FSM);

    const int nX = MROWS * CHID, nW = CHID * CHID;
    dim3 ggrid((MROWS + 127) / 128, CHID / 128);

    cvt_split<<<(nX + 255) / 256, 256>>>(query, xh, xl, nX);
    cvt_w_proj<<<(nW + 255) / 256, 256>>>(Wq, wh, wl);
    gemm_mma<0><<<ggrid, 256, GEMM_SMEM_BYTES>>>(xh, xl, wh, wl, bq, nullptr, qh, ql);

    cvt_split<<<(nX + 255) / 256, 256>>>(key, xh, xl, nX);
    cvt_w_proj<<<(nW + 255) / 256, 256>>>(Wk, wh, wl);
    gemm_mma<0><<<ggrid, 256, GEMM_SMEM_BYTES>>>(xh, xl, wh, wl, bk, nullptr, kh, kl);

    cvt_split<<<(nX + 255) / 256, 256>>>(value, xh, xl, nX);
    cvt_w_proj<<<(nW + 255) / 256, 256>>>(Wv, wh, wl);
    gemm_mma<2><<<ggrid, 256, GEMM_SMEM_BYTES>>>(xh, xl, wh, wl, bv, nullptr, vh, vl);

    flash_mma<<<dim3(24, CNH, CB), 256, FSM>>>(posk, posv);

    cvt_w_fc<<<(nW + 255) / 256, 256>>>(Wfc, wh, wl);
    gemm_mma<3><<<ggrid, 256, GEMM_SMEM_BYTES>>>(xh, xl, wh, wl, bfc, out, nullptr, nullptr);
}

// round 15
// speedup vs baseline: 1.7312x; 1.0351x over previous
#include <cuda_runtime.h>
#include <cuda_bf16.h>
#include <cuda_fp16.h>
#include <stdint.h>

#define CB 4
#define CS 1500
#define CHID 1024
#define CNH 16
#define CDH 64
#define NREL 129
#define MROWS (CB*CS)      // 6000
#define SPAD 1536          // padded S for V^T rows

// ---------------- scratch (device globals; zero-initialized) ----------------
__device__ __align__(16) __nv_bfloat16 g_qh[CB*CNH*CS*CDH];
__device__ __align__(16) __nv_bfloat16 g_ql[CB*CNH*CS*CDH];
__device__ __align__(16) __nv_bfloat16 g_kh[CB*CNH*CS*CDH];
__device__ __align__(16) __nv_bfloat16 g_kl[CB*CNH*CS*CDH];
__device__ __align__(16) __nv_bfloat16 g_vh[CB*CNH*CDH*SPAD];  // V^T [B,NH,DH,SPAD]
__device__ __align__(16) __nv_bfloat16 g_vl[CB*CNH*CDH*SPAD];
__device__ __align__(16) __nv_bfloat16 g_xh[MROWS*CHID];       // GEMM A / hidden
__device__ __align__(16) __nv_bfloat16 g_xl[MROWS*CHID];
__device__ __align__(16) __nv_bfloat16 g_wh[CHID*CHID];
__device__ __align__(16) __nv_bfloat16 g_wl[CHID*CHID];

// ---------------- helpers ----------------
__device__ __forceinline__ uint32_t smem_u32(const void* p) {
    uint32_t a;
    asm("{ .reg .u64 t; cvta.to.shared.u64 t, %1; cvt.u32.u64 %0, t; }" : "=r"(a) : "l"(p));
    return a;
}
__device__ __forceinline__ void ldsm4(uint32_t* r, uint32_t a) {
    asm volatile("ldmatrix.sync.aligned.m8n8.x4.shared.b16 {%0,%1,%2,%3}, [%4];"
                 : "=r"(r[0]), "=r"(r[1]), "=r"(r[2]), "=r"(r[3]) : "r"(a));
}
__device__ __forceinline__ void mma16816(float* c, const uint32_t* a, const uint32_t* b) {
    asm volatile(
        "mma.sync.aligned.m16n8k16.row.col.f32.bf16.bf16.f32 "
        "{%0,%1,%2,%3}, {%4,%5,%6,%7}, {%8,%9}, {%0,%1,%2,%3};"
        : "+f"(c[0]), "+f"(c[1]), "+f"(c[2]), "+f"(c[3])
        : "r"(a[0]), "r"(a[1]), "r"(a[2]), "r"(a[3]), "r"(b[0]), "r"(b[1]));
}
__device__ __forceinline__ void cpa16(uint32_t dst, const void* src, int sz) {
    asm volatile("cp.async.cg.shared.global [%0], [%1], 16, %2;"
                 :: "r"(dst), "l"(src), "r"(sz) : "memory");
}
#define CPA_COMMIT() asm volatile("cp.async.commit_group;" ::: "memory")
#define CPA_WAIT0()  asm volatile("cp.async.wait_group 0;" ::: "memory")
// FFMA-only exp (no MUFU). valid for x <= 0, clamped at 2^-120.
__device__ __forceinline__ float fexp(float x) {
    float y = fmaxf(x * 1.4426950408889634f, -120.0f);
    float z = y + 12582912.0f;
    int   i = __float_as_int(z) - 0x4B400000;
    float f = y - (z - 12582912.0f);
    float p =      1.3333558146e-3f;
    p = fmaf(p, f, 9.6181291076e-3f);
    p = fmaf(p, f, 5.5504108665e-2f);
    p = fmaf(p, f, 2.4022650696e-1f);
    p = fmaf(p, f, 6.9314718056e-1f);
    p = fmaf(p, f, 1.0f);
    return __int_as_float(__float_as_int(p) + (i << 23));
}
__device__ __forceinline__ uint32_t packbf(float a, float b) {
    __nv_bfloat162 t = __halves2bfloat162(__float2bfloat16(a), __float2bfloat16(b));
    return *(uint32_t*)&t;
}

// ---------------- conversion kernels ----------------
__global__ void cvt_split(const float* __restrict__ x,
                          __nv_bfloat16* __restrict__ hi, __nv_bfloat16* __restrict__ lo, int n) {
    int i = blockIdx.x * blockDim.x + threadIdx.x;
    if (i < n) {
        float v = x[i];
        __nv_bfloat16 h = __float2bfloat16(v);
        hi[i] = h; lo[i] = __float2bfloat16(v - __bfloat162float(h));
    }
}
__global__ void cvt_w_proj(const float* __restrict__ W,
                           __nv_bfloat16* __restrict__ hi, __nv_bfloat16* __restrict__ lo) {
    int i = blockIdx.x * blockDim.x + threadIdx.x;
    if (i < CHID * CHID) {
        int col = i >> 10, k = i & 1023;
        float v = W[((size_t)(col >> 6) * CHID + k) * CDH + (col & 63)];
        __nv_bfloat16 h = __float2bfloat16(v);
        hi[i] = h; lo[i] = __float2bfloat16(v - __bfloat162float(h));
    }
}
__global__ void cvt_w_fc(const float* __restrict__ W,
                         __nv_bfloat16* __restrict__ hi, __nv_bfloat16* __restrict__ lo) {
    int i = blockIdx.x * blockDim.x + threadIdx.x;
    if (i < CHID * CHID) {
        int col = i >> 10, k = i & 1023;
        float v = W[(size_t)k * CHID + col];
        __nv_bfloat16 h = __float2bfloat16(v);
        hi[i] = h; lo[i] = __float2bfloat16(v - __bfloat162float(h));
    }
}

// ============================================================================
// mma.sync split-bf16 GEMM (validated core, unchanged).
// ============================================================================
#define SPITCH 144
#define TILE_BYTES (128 * SPITCH)
#define GEMM_SMEM_BYTES (4 * TILE_BYTES)

template<int MODE>
__global__ __launch_bounds__(256, 1) void gemm_mma(
    const __nv_bfloat16* __restrict__ Xh, const __nv_bfloat16* __restrict__ Xl,
    const __nv_bfloat16* __restrict__ Wh, const __nv_bfloat16* __restrict__ Wl,
    const float* __restrict__ bias, float* __restrict__ outf,
    __nv_bfloat16* __restrict__ oh, __nv_bfloat16* __restrict__ ol)
{
    extern __shared__ char smem[];
    uint32_t sbase = smem_u32(smem);
    int tid = threadIdx.x, wid = tid >> 5, lid = tid & 31;
    int wm = wid & 1, wn = wid >> 1;
    int m0 = blockIdx.x * 128, n0 = blockIdx.y * 128;

    float C[4][4][4];
    #pragma unroll
    for (int i = 0; i < 4; i++)
        #pragma unroll
        for (int j = 0; j < 4; j++)
            #pragma unroll
            for (int r = 0; r < 4; r++) C[i][j][r] = 0.f;

    uint32_t a_row = wm * 64 + (lid & 15), a_koff = (lid >> 4) * 8;
    uint32_t b_n = wn * 32 + ((lid >> 4) * 8) + (lid & 7);
    uint32_t b_koff = ((lid >> 3) & 1) * 8;

    for (int c = 0; c < CHID / 64; c++) {
        __syncthreads();
        #pragma unroll
        for (int t = 0; t < 4; t++) {
            const __nv_bfloat16* src = (t == 0) ? Xh : (t == 1) ? Xl : (t == 2) ? Wh : Wl;
            const bool isA = (t < 2);
            char* db = smem + t * TILE_BYTES;
            #pragma unroll
            for (int p = 0; p < 4; p++) {
                int slot = tid + p * 256;
                int row = slot >> 3, i8 = slot & 7;
                int gr = (isA ? m0 : n0) + row;
                uint4 v = make_uint4(0, 0, 0, 0);
                if (!isA || gr < MROWS)
                    v = ((const uint4*)(src + (size_t)gr * CHID + c * 64))[i8];
                *(uint4*)(db + row * SPITCH + i8 * 16) = v;
            }
        }
        __syncthreads();
        #pragma unroll
        for (int ks = 0; ks < 4; ks++) {
            uint32_t Ah[4][4], Al[4][4], Bh[4][2], Bl[4][2];
            #pragma unroll
            for (int i = 0; i < 4; i++) {
                uint32_t off = (a_row + i * 16) * SPITCH + (ks * 16 + a_koff) * 2;
                ldsm4(Ah[i], sbase + 0 * TILE_BYTES + off);
                ldsm4(Al[i], sbase + 1 * TILE_BYTES + off);
            }
            #pragma unroll
            for (int j2 = 0; j2 < 2; j2++) {
                uint32_t off = (b_n + j2 * 16) * SPITCH + (ks * 16 + b_koff) * 2;
                uint32_t tmp[4];
                ldsm4(tmp, sbase + 2 * TILE_BYTES + off);
                Bh[j2*2][0] = tmp[0]; Bh[j2*2][1] = tmp[1];
                Bh[j2*2+1][0] = tmp[2]; Bh[j2*2+1][1] = tmp[3];
                ldsm4(tmp, sbase + 3 * TILE_BYTES + off);
                Bl[j2*2][0] = tmp[0]; Bl[j2*2][1] = tmp[1];
                Bl[j2*2+1][0] = tmp[2]; Bl[j2*2+1][1] = tmp[3];
            }
            #pragma unroll
            for (int i = 0; i < 4; i++)
                #pragma unroll
                for (int j = 0; j < 4; j++) {
                    mma16816(C[i][j], Ah[i], Bh[j]);
                    mma16816(C[i][j], Ah[i], Bl[j]);
                    mma16816(C[i][j], Al[i], Bh[j]);
                }
        }
    }
    int r = lid >> 2, cg = (lid & 3) * 2;
    #pragma unroll
    for (int i = 0; i < 4; i++) {
        int rows[2] = { m0 + wm*64 + i*16 + r, m0 + wm*64 + i*16 + r + 8 };
        #pragma unroll
        for (int j = 0; j < 4; j++) {
            int col = n0 + wn * 32 + j * 8 + cg;
            float b0 = bias[col], b1 = bias[col + 1];
            float vx[2] = { C[i][j][0] + b0, C[i][j][2] + b0 };
            float vy[2] = { C[i][j][1] + b1, C[i][j][3] + b1 };
            #pragma unroll
            for (int h = 0; h < 2; h++) {
                int row = rows[h];
                if (row >= MROWS) continue;
                if (MODE == 3) {
                    *(float2*)(outf + (size_t)row * CHID + col) = make_float2(vx[h], vy[h]);
                } else {
                    int bi = row / CS, s = row - bi * CS;
                    int n = col >> 6, d = col & 63;
                    __nv_bfloat16 hx = __float2bfloat16(vx[h]), hy = __float2bfloat16(vy[h]);
                    __nv_bfloat16 lx = __float2bfloat16(vx[h] - __bfloat162float(hx));
                    __nv_bfloat16 ly = __float2bfloat16(vy[h] - __bfloat162float(hy));
                    if (MODE == 0) {
                        size_t a = (((size_t)(bi * CNH + n)) * CS + s) * CDH + d;
                        *(__nv_bfloat162*)(oh + a) = __halves2bfloat162(hx, hy);
                        *(__nv_bfloat162*)(ol + a) = __halves2bfloat162(lx, ly);
                    } else {
                        size_t base = (size_t)(bi * CNH + n) * CDH;
                        oh[(base + d) * SPAD + s] = hx; oh[(base + d + 1) * SPAD + s] = hy;
                        ol[(base + d) * SPAD + s] = lx; ol[(base + d + 1) * SPAD + s] = ly;
                    }
                }
            }
        }
    }
}

// ============================================================================
// Tensor-core flash attention + Shaw bias. q-tile=128, warp-owned rows.
// 8 warps each own 16 q-rows x full 64-k width. ONE barrier per k-tile.
// Softmax state fully register-resident (quad shuffles only).
// ============================================================================
#define FP 144
#define OQH 0                   // 128 x 144 = 18432
#define OQL 18432
#define OKB 36864               // 2 buffers x 36864 (KH,KL,VH,VL each 64x144)
#define ORS 110592              // half [128][132] = 33792
#define OPV 144384              // float [129][68] = 35088
#define OPB 179472              // float [128][68] = 34816
#define FSM 214288

__global__ __launch_bounds__(256, 1) void flash_mma(
    const float* __restrict__ posk, const float* __restrict__ posv)
{
    extern __shared__ char sm[];
    uint32_t sb = smem_u32(sm);
    __half* Rs  = (__half*)(sm + ORS);
    float*  PVt = (float*)(sm + OPV);
    float*  Pb  = (float*)(sm + OPB);

    int qt = blockIdx.x, hn = blockIdx.y, bb = blockIdx.z;
    int q0 = qt * 128;
    size_t ho = ((size_t)(bb * CNH + hn)) * CS * CDH;
    size_t hv = ((size_t)(bb * CNH + hn)) * CDH * SPAD;
    int tid = threadIdx.x, wid = tid >> 5, lid = tid & 31;
    int qr = lid >> 2, qc = (lid & 3) * 2;
    int row0 = wid * 16 + qr, row1 = row0 + 8;
    int qg0 = q0 + row0, qg1 = q0 + row1;

    auto issue_kv = [&](int kt2, uint32_t kb) {
        #pragma unroll
        for (int p = 0; p < 2; p++) {
            int slot = tid + p * 256;
            int r = slot >> 3, i8 = slot & 7;
            int kg = kt2 * 64 + r;
            int sz = (kg < CS) ? 16 : 0;
            int kgc = (kg < CS) ? kg : (CS - 1);
            cpa16(sb + kb + r * FP + i8 * 16,         g_kh + ho + (size_t)kgc * CDH + i8 * 8, sz);
            cpa16(sb + kb + 9216 + r * FP + i8 * 16,  g_kl + ho + (size_t)kgc * CDH + i8 * 8, sz);
            cpa16(sb + kb + 18432 + r * FP + i8 * 16, g_vh + hv + (size_t)r * SPAD + kt2 * 64 + i8 * 8, 16);
            cpa16(sb + kb + 27648 + r * FP + i8 * 16, g_vl + hv + (size_t)r * SPAD + kt2 * 64 + i8 * 8, 16);
        }
    };
    issue_kv(0, OKB);
    CPA_COMMIT();

    // ---- prologue: Q tiles, posk, fp32 Q, Rs table (fp16), posv ----
    #pragma unroll
    for (int p = 0; p < 4; p++) {
        int slot = tid + p * 256;
        int r = slot >> 3, i8 = slot & 7;
        int qg = q0 + r;
        uint4 vh = make_uint4(0,0,0,0), vl = vh;
        if (qg < CS) {
            vh = ((const uint4*)(g_qh + ho + (size_t)qg * CDH))[i8];
            vl = ((const uint4*)(g_ql + ho + (size_t)qg * CDH))[i8];
        }
        *(uint4*)(sm + OQH + r * FP + i8 * 16) = vh;
        *(uint4*)(sm + OQL + r * FP + i8 * 16) = vl;
    }
    for (int idx = tid; idx < NREL * 64; idx += 256)
        PVt[(idx >> 6) * 68 + (idx & 63)] = posk[idx];
    __syncthreads();
    for (int idx = tid; idx < 128 * 64; idx += 256) {
        int r = idx >> 6, d = idx & 63;
        Pb[r * 68 + d] = __bfloat162float(*(__nv_bfloat16*)(sm + OQH + r * FP + d * 2))
                       + __bfloat162float(*(__nv_bfloat16*)(sm + OQL + r * FP + d * 2));
    }
    __syncthreads();
    for (int t = tid; t < 128 * 33; t += 256) {
        int qq = t / 33, jg = t - qq * 33, j0 = jg * 4;
        const float4* q4 = (const float4*)(Pb + qq * 68);
        if (jg < 32) {
            const float4 *p0 = (const float4*)(PVt + (j0+0)*68), *p1 = (const float4*)(PVt + (j0+1)*68);
            const float4 *p2 = (const float4*)(PVt + (j0+2)*68), *p3 = (const float4*)(PVt + (j0+3)*68);
            float a0=0,a1=0,a2=0,a3=0;
            #pragma unroll
            for (int d4 = 0; d4 < 16; d4++) {
                float4 qv = q4[d4]; float4 x;
                x=p0[d4]; a0+=qv.x*x.x+qv.y*x.y+qv.z*x.z+qv.w*x.w;
                x=p1[d4]; a1+=qv.x*x.x+qv.y*x.y+qv.z*x.z+qv.w*x.w;
                x=p2[d4]; a2+=qv.x*x.x+qv.y*x.y+qv.z*x.z+qv.w*x.w;
                x=p3[d4]; a3+=qv.x*x.x+qv.y*x.y+qv.z*x.z+qv.w*x.w;
            }
            Rs[qq*132+j0]   = __float2half(a0); Rs[qq*132+j0+1] = __float2half(a1);
            Rs[qq*132+j0+2] = __float2half(a2); Rs[qq*132+j0+3] = __float2half(a3);
        } else {
            const float4* p0 = (const float4*)(PVt + 128 * 68);
            float a0 = 0.f;
            #pragma unroll
            for (int d4 = 0; d4 < 16; d4++) {
                float4 qv = q4[d4], x = p0[d4];
                a0 += qv.x*x.x + qv.y*x.y + qv.z*x.z + qv.w*x.w;
            }
            Rs[qq * 132 + 128] = __float2half(a0);
        }
    }
    __syncthreads();
    for (int idx = tid; idx < NREL * 64; idx += 256)
        PVt[(idx >> 6) * 68 + (idx & 63)] = posv[idx];

    // register-resident per-row softmax state (replicated across quad)
    float rm0 = -1e30f, rm1 = -1e30f, rl0 = 0.f, rl1 = 0.f;
    float rL0 = 0.f, rL1 = 0.f, rH0 = 0.f, rH1 = 0.f;
    float O[8][4];
    #pragma unroll
    for (int nf = 0; nf < 8; nf++)
        #pragma unroll
        for (int c = 0; c < 4; c++) O[nf][c] = 0.f;

    uint32_t a_off = (uint32_t)((wid * 16 + (lid & 15)) * FP) + ((lid >> 4) * 8) * 2;
    uint32_t bk_row = ((lid >> 4) * 8) + (lid & 7);
    uint32_t bk_koff = ((lid >> 3) & 1) * 8;
    int wbase = q0 + wid * 16;           // warp's first q row

    for (int kt = 0; kt < 24; kt++) {
        uint32_t kb = OKB + (kt & 1) * 36864;
        CPA_WAIT0();
        __syncthreads();                                   // only barrier per tile
        if (kt < 23) { issue_kv(kt + 1, OKB + ((kt + 1) & 1) * 36864); CPA_COMMIT(); }

        // ---- S = QK^T (3-term split), full 64 k-cols per warp ----
        float S[8][4];
        #pragma unroll
        for (int nf = 0; nf < 8; nf++)
            #pragma unroll
            for (int c = 0; c < 4; c++) S[nf][c] = 0.f;
        #pragma unroll
        for (int ks = 0; ks < 4; ks++) {
            uint32_t Ah[4], Al[4];
            ldsm4(Ah, sb + OQH + a_off + ks * 32);
            ldsm4(Al, sb + OQL + a_off + ks * 32);
            #pragma unroll
            for (int j2 = 0; j2 < 4; j2++) {
                uint32_t off = (bk_row + j2 * 16) * FP + (ks * 16 + bk_koff) * 2;
                uint32_t th[4], tl[4];
                ldsm4(th, sb + kb + off);
                ldsm4(tl, sb + kb + 9216 + off);
                uint32_t B0h[2]={th[0],th[1]}, B1h[2]={th[2],th[3]};
                uint32_t B0l[2]={tl[0],tl[1]}, B1l[2]={tl[2],tl[3]};
                mma16816(S[j2*2], Ah, B0h); mma16816(S[j2*2], Ah, B0l); mma16816(S[j2*2], Al, B0h);
                mma16816(S[j2*2+1], Ah, B1h); mma16816(S[j2*2+1], Ah, B1l); mma16816(S[j2*2+1], Al, B1h);
            }
        }
        // ---- bias + scale + mask + quad max ----
        float m0v = -1e30f, m1v = -1e30f;
        #pragma unroll
        for (int nf = 0; nf < 8; nf++) {
            int colb = nf * 8 + qc;
            int kg0 = kt * 64 + colb, kg1 = kg0 + 1;
            int j00 = min(max(kg0-qg0,-64),64)+64, j01 = min(max(kg1-qg0,-64),64)+64;
            int j10 = min(max(kg0-qg1,-64),64)+64, j11 = min(max(kg1-qg1,-64),64)+64;
            float s0 = (S[nf][0] + __half2float(Rs[row0*132+j00])) * 0.125f;
            float s1 = (S[nf][1] + __half2float(Rs[row0*132+j01])) * 0.125f;
            float s2 = (S[nf][2] + __half2float(Rs[row1*132+j10])) * 0.125f;
            float s3 = (S[nf][3] + __half2float(Rs[row1*132+j11])) * 0.125f;
            if (kg0 >= CS) { s0 = -1e30f; s2 = -1e30f; }
            if (kg1 >= CS) { s1 = -1e30f; s3 = -1e30f; }
            S[nf][0]=s0; S[nf][1]=s1; S[nf][2]=s2; S[nf][3]=s3;
            m0v = fmaxf(m0v, fmaxf(s0, s1));
            m1v = fmaxf(m1v, fmaxf(s2, s3));
        }
        m0v = fmaxf(m0v, __shfl_xor_sync(~0u, m0v, 1)); m0v = fmaxf(m0v, __shfl_xor_sync(~0u, m0v, 2));
        m1v = fmaxf(m1v, __shfl_xor_sync(~0u, m1v, 1)); m1v = fmaxf(m1v, __shfl_xor_sync(~0u, m1v, 2));

        float mn0 = fmaxf(rm0, m0v), mn1 = fmaxf(rm1, m1v);
        float al0 = fexp(rm0 - mn0), al1 = fexp(rm1 - mn1);
        rm0 = mn0; rm1 = mn1;
        #pragma unroll
        for (int nf = 0; nf < 8; nf++) { O[nf][0]*=al0; O[nf][1]*=al0; O[nf][2]*=al1; O[nf][3]*=al1; }

        int klo = max(0, wbase - 63 - kt * 64);
        int khi = min(64, wbase + 15 + 64 - kt * 64 + 1);
        bool band = (khi > klo);
        float s0a=0,s1a=0,l0a=0,l1a=0,h0a=0,h1a=0;
        uint32_t PhA[4][4], PlA[4][4];
        #pragma unroll
        for (int nf = 0; nf < 8; nf++) {
            int colb = nf * 8 + qc;
            int kg = kt * 64 + colb;
            float p00 = fexp(S[nf][0]-mn0), p01 = fexp(S[nf][1]-mn0);
            float p10 = fexp(S[nf][2]-mn1), p11 = fexp(S[nf][3]-mn1);
            s0a += p00 + p01; s1a += p10 + p11;
            int e0 = kg - qg0, e1 = kg - qg1;
            l0a += (e0<=-64?p00:0.f) + (e0+1<=-64?p01:0.f);
            h0a += (e0>= 64?p00:0.f) + (e0+1>= 64?p01:0.f);
            l1a += (e1<=-64?p10:0.f) + (e1+1<=-64?p11:0.f);
            h1a += (e1>= 64?p10:0.f) + (e1+1>= 64?p11:0.f);
            float f00 = __bfloat162float(__float2bfloat16(p00));
            float f01 = __bfloat162float(__float2bfloat16(p01));
            float f10 = __bfloat162float(__float2bfloat16(p10));
            float f11 = __bfloat162float(__float2bfloat16(p11));
            int kc = nf >> 1, hx = (nf & 1) * 2;
            PhA[kc][hx]   = packbf(f00, f01);
            PhA[kc][hx+1] = packbf(f10, f11);
            PlA[kc][hx]   = packbf(p00 - f00, p01 - f01);
            PlA[kc][hx+1] = packbf(p10 - f10, p11 - f11);
            if (band) {
                *(float2*)&Pb[row0*68+colb] = make_float2(p00, p01);
                *(float2*)&Pb[row1*68+colb] = make_float2(p10, p11);
            }
        }
        s0a += __shfl_xor_sync(~0u,s0a,1); s0a += __shfl_xor_sync(~0u,s0a,2);
        s1a += __shfl_xor_sync(~0u,s1a,1); s1a += __shfl_xor_sync(~0u,s1a,2);
        l0a += __shfl_xor_sync(~0u,l0a,1); l0a += __shfl_xor_sync(~0u,l0a,2);
        l1a += __shfl_xor_sync(~0u,l1a,1); l1a += __shfl_xor_sync(~0u,l1a,2);
        h0a += __shfl_xor_sync(~0u,h0a,1); h0a += __shfl_xor_sync(~0u,h0a,2);
        h1a += __shfl_xor_sync(~0u,h1a,1); h1a += __shfl_xor_sync(~0u,h1a,2);
        rl0 = rl0*al0 + s0a; rl1 = rl1*al1 + s1a;
        rL0 = rL0*al0 + l0a; rL1 = rL1*al1 + l1a;
        rH0 = rH0*al0 + h0a; rH1 = rH1*al1 + h1a;
        if (band) __syncwarp();

        // ---- O += P @ V (full 64 k per warp, 3-term split) ----
        #pragma unroll
        for (int kc = 0; kc < 4; kc++) {
            #pragma unroll
            for (int jd = 0; jd < 4; jd++) {
                uint32_t off = (jd*16 + bk_row) * FP + (kc*16 + bk_koff) * 2;
                uint32_t th[4], tl[4];
                ldsm4(th, sb + kb + 18432 + off);
                ldsm4(tl, sb + kb + 27648 + off);
                uint32_t B0h[2]={th[0],th[1]}, B1h[2]={th[2],th[3]};
                uint32_t B0l[2]={tl[0],tl[1]}, B1l[2]={tl[2],tl[3]};
                mma16816(O[jd*2], PhA[kc], B0h); mma16816(O[jd*2], PhA[kc], B0l);
                mma16816(O[jd*2], PlA[kc], B0h);
                mma16816(O[jd*2+1], PhA[kc], B1h); mma16816(O[jd*2+1], PhA[kc], B1l);
                mma16816(O[jd*2+1], PlA[kc], B1h);
            }
        }
        // ---- banded pos_v term, clamped k-range ----
        if (band) {
            for (int k = klo; k < khi; k++) {
                int kg = kt * 64 + k;
                float p0 = Pb[row0*68+k], p1 = Pb[row1*68+k];
                int d0 = kg - qg0, d1 = kg - qg1;
                bool b0 = d0 > -64 && d0 < 64, b1 = d1 > -64 && d1 < 64;
                const float* r0p = PVt + (d0 + 64) * 68;
                const float* r1p = PVt + (d1 + 64) * 68;
                #pragma unroll
                for (int nf = 0; nf < 8; nf++) {
                    int col = nf * 8 + qc;
                    if (b0) { float2 v = *(const float2*)(r0p + col); O[nf][0] += p0*v.x; O[nf][1] += p0*v.y; }
                    if (b1) { float2 v = *(const float2*)(r1p + col); O[nf][2] += p1*v.x; O[nf][3] += p1*v.y; }
                }
            }
        }
    }

    // ---- epilogue: per-warp direct write (no cross-warp reduce) ----
    float il0 = 1.f / rl0, il1 = 1.f / rl1;
    size_t ob0 = ((size_t)(bb * CS + qg0)) * CHID + hn * 64;
    size_t ob1 = ((size_t)(bb * CS + qg1)) * CHID + hn * 64;
    #pragma unroll
    for (int nf = 0; nf < 8; nf++) {
        int col = nf * 8 + qc;
        float2 v0 = *(float2*)&PVt[col];
        float2 v2 = *(float2*)&PVt[128*68+col];
        float o00 = (O[nf][0] + rL0*v0.x + rH0*v2.x) * il0;
        float o01 = (O[nf][1] + rL0*v0.y + rH0*v2.y) * il0;
        float o10 = (O[nf][2] + rL1*v0.x + rH1*v2.x) * il1;
        float o11 = (O[nf][3] + rL1*v0.y + rH1*v2.y) * il1;
        if (qg0 < CS) {
            __nv_bfloat16 hx = __float2bfloat16(o00), hy = __float2bfloat16(o01);
            *(__nv_bfloat162*)(g_xh + ob0 + col) = __halves2bfloat162(hx, hy);
            *(__nv_bfloat162*)(g_xl + ob0 + col) = __halves2bfloat162(
                __float2bfloat16(o00 - __bfloat162float(hx)),
                __float2bfloat16(o01 - __bfloat162float(hy)));
        }
        if (qg1 < CS) {
            __nv_bfloat16 hx = __float2bfloat16(o10), hy = __float2bfloat16(o11);
            *(__nv_bfloat162*)(g_xh + ob1 + col) = __halves2bfloat162(hx, hy);
            *(__nv_bfloat162*)(g_xl + ob1 + col) = __halves2bfloat162(
                __float2bfloat16(o10 - __bfloat162float(hx)),
                __float2bfloat16(o11 - __bfloat162float(hy)));
        }
    }
}

// ============================================================================
extern "C" void kernel_launch(void* const* d_in, const int* in_sizes, int n_in,
                              void* d_out, int out_size)
{
    const float* query = (const float*)d_in[0];
    const float* key   = (const float*)d_in[1];
    const float* value = (const float*)d_in[2];
    const float* Wq    = (const float*)d_in[3];
    const float* bq    = (const float*)d_in[4];
    const float* Wk    = (const float*)d_in[5];
    const float* bk    = (const float*)d_in[6];
    const float* Wv    = (const float*)d_in[7];
    const float* bv    = (const float*)d_in[8];
    const float* posk  = (const float*)d_in[9];
    const float* posv  = (const float*)d_in[10];
    const float* Wfc   = (const float*)d_in[11];
    const float* bfc   = (const float*)d_in[12];
    float* out = (float*)d_out;

    __nv_bfloat16 *xh, *xl, *wh, *wl, *qh, *ql, *kh, *kl, *vh, *vl;
    cudaGetSymbolAddress((void**)&xh, g_xh);
    cudaGetSymbolAddress((void**)&xl, g_xl);
    cudaGetSymbolAddress((void**)&wh, g_wh);
    cudaGetSymbolAddress((void**)&wl, g_wl);
    cudaGetSymbolAddress((void**)&qh, g_qh);
    cudaGetSymbolAddress((void**)&ql, g_ql);
    cudaGetSymbolAddress((void**)&kh, g_kh);
    cudaGetSymbolAddress((void**)&kl, g_kl);
    cudaGetSymbolAddress((void**)&vh, g_vh);
    cudaGetSymbolAddress((void**)&vl, g_vl);

    cudaFuncSetAttribute(gemm_mma<0>, cudaFuncAttributeMaxDynamicSharedMemorySize, GEMM_SMEM_BYTES);
    cudaFuncSetAttribute(gemm_mma<2>, cudaFuncAttributeMaxDynamicSharedMemorySize, GEMM_SMEM_BYTES);
    cudaFuncSetAttribute(gemm_mma<3>, cudaFuncAttributeMaxDynamicSharedMemorySize, GEMM_SMEM_BYTES);
    cudaFuncSetAttribute(flash_mma, cudaFuncAttributeMaxDynamicSharedMemorySize, FSM);

    const int nX = MROWS * CHID, nW = CHID * CHID;
    dim3 ggrid((MROWS + 127) / 128, CHID / 128);

    cvt_split<<<(nX + 255) / 256, 256>>>(query, xh, xl, nX);
    cvt_w_proj<<<(nW + 255) / 256, 256>>>(Wq, wh, wl);
    gemm_mma<0><<<ggrid, 256, GEMM_SMEM_BYTES>>>(xh, xl, wh, wl, bq, nullptr, qh, ql);

    cvt_split<<<(nX + 255) / 256, 256>>>(key, xh, xl, nX);
    cvt_w_proj<<<(nW + 255) / 256, 256>>>(Wk, wh, wl);
    gemm_mma<0><<<ggrid, 256, GEMM_SMEM_BYTES>>>(xh, xl, wh, wl, bk, nullptr, kh, kl);

    cvt_split<<<(nX + 255) / 256, 256>>>(value, xh, xl, nX);
    cvt_w_proj<<<(nW + 255) / 256, 256>>>(Wv, wh, wl);
    gemm_mma<2><<<ggrid, 256, GEMM_SMEM_BYTES>>>(xh, xl, wh, wl, bv, nullptr, vh, vl);

    flash_mma<<<dim3(12, CNH, CB), 256, FSM>>>(posk, posv);

    cvt_w_fc<<<(nW + 255) / 256, 256>>>(Wfc, wh, wl);
    gemm_mma<3><<<ggrid, 256, GEMM_SMEM_BYTES>>>(xh, xl, wh, wl, bfc, out, nullptr, nullptr);
}

// round 17
// speedup vs baseline: 1.9842x; 1.1461x over previous
#include <cuda_runtime.h>
#include <cuda_bf16.h>
#include <cuda_fp16.h>
#include <stdint.h>

#define CB 4
#define CS 1500
#define CHID 1024
#define CNH 16
#define CDH 64
#define NREL 129
#define MROWS (CB*CS)      // 6000
#define SPAD 1536

// ---------------- scratch (device globals) ----------------
__device__ __align__(16) __half g_qf[CB*CNH*CS*CDH];          // fp16 Q (pre-scaled by 1/8)
__device__ __align__(16) __half g_kf[CB*CNH*CS*CDH];          // fp16 K
__device__ __align__(16) __half g_vf[CB*CNH*CDH*SPAD];        // fp16 V^T [B,NH,DH,SPAD]
__device__ __align__(16) __nv_bfloat16 g_xh[MROWS*CHID];      // GEMM A / hidden (bf16 hi/lo)
__device__ __align__(16) __nv_bfloat16 g_xl[MROWS*CHID];
__device__ __align__(16) __nv_bfloat16 g_wh[CHID*CHID];
__device__ __align__(16) __nv_bfloat16 g_wl[CHID*CHID];

// ---------------- helpers ----------------
__device__ __forceinline__ uint32_t smem_u32(const void* p) {
    uint32_t a;
    asm("{ .reg .u64 t; cvta.to.shared.u64 t, %1; cvt.u32.u64 %0, t; }" : "=r"(a) : "l"(p));
    return a;
}
__device__ __forceinline__ void ldsm4(uint32_t* r, uint32_t a) {
    asm volatile("ldmatrix.sync.aligned.m8n8.x4.shared.b16 {%0,%1,%2,%3}, [%4];"
                 : "=r"(r[0]), "=r"(r[1]), "=r"(r[2]), "=r"(r[3]) : "r"(a));
}
__device__ __forceinline__ void mma16816(float* c, const uint32_t* a, const uint32_t* b) {
    asm volatile(
        "mma.sync.aligned.m16n8k16.row.col.f32.bf16.bf16.f32 "
        "{%0,%1,%2,%3}, {%4,%5,%6,%7}, {%8,%9}, {%0,%1,%2,%3};"
        : "+f"(c[0]), "+f"(c[1]), "+f"(c[2]), "+f"(c[3])
        : "r"(a[0]), "r"(a[1]), "r"(a[2]), "r"(a[3]), "r"(b[0]), "r"(b[1]));
}
__device__ __forceinline__ void mma16816h(float* c, const uint32_t* a, const uint32_t* b) {
    asm volatile(
        "mma.sync.aligned.m16n8k16.row.col.f32.f16.f16.f32 "
        "{%0,%1,%2,%3}, {%4,%5,%6,%7}, {%8,%9}, {%0,%1,%2,%3};"
        : "+f"(c[0]), "+f"(c[1]), "+f"(c[2]), "+f"(c[3])
        : "r"(a[0]), "r"(a[1]), "r"(a[2]), "r"(a[3]), "r"(b[0]), "r"(b[1]));
}
__device__ __forceinline__ void cpa16(uint32_t dst, const void* src, int sz) {
    asm volatile("cp.async.cg.shared.global [%0], [%1], 16, %2;"
                 :: "r"(dst), "l"(src), "r"(sz) : "memory");
}
#define CPA_COMMIT() asm volatile("cp.async.commit_group;" ::: "memory")
#define CPA_WAIT0()  asm volatile("cp.async.wait_group 0;" ::: "memory")
__device__ __forceinline__ float fexp(float x) {
    float y = fmaxf(x * 1.4426950408889634f, -120.0f);
    float z = y + 12582912.0f;
    int   i = __float_as_int(z) - 0x4B400000;
    float f = y - (z - 12582912.0f);
    float p =      1.3333558146e-3f;
    p = fmaf(p, f, 9.6181291076e-3f);
    p = fmaf(p, f, 5.5504108665e-2f);
    p = fmaf(p, f, 2.4022650696e-1f);
    p = fmaf(p, f, 6.9314718056e-1f);
    p = fmaf(p, f, 1.0f);
    return __int_as_float(__float_as_int(p) + (i << 23));
}
__device__ __forceinline__ uint32_t packh2(float a, float b) {
    __half2 t = __floats2half2_rn(a, b);
    return *(uint32_t*)&t;
}

// ---------------- conversion kernels ----------------
__global__ void cvt_split(const float* __restrict__ x,
                          __nv_bfloat16* __restrict__ hi, __nv_bfloat16* __restrict__ lo, int n) {
    int i = blockIdx.x * blockDim.x + threadIdx.x;
    if (i < n) {
        float v = x[i];
        __nv_bfloat16 h = __float2bfloat16(v);
        hi[i] = h; lo[i] = __float2bfloat16(v - __bfloat162float(h));
    }
}
__global__ void cvt_w_proj(const float* __restrict__ W,
                           __nv_bfloat16* __restrict__ hi, __nv_bfloat16* __restrict__ lo) {
    int i = blockIdx.x * blockDim.x + threadIdx.x;
    if (i < CHID * CHID) {
        int col = i >> 10, k = i & 1023;
        float v = W[((size_t)(col >> 6) * CHID + k) * CDH + (col & 63)];
        __nv_bfloat16 h = __float2bfloat16(v);
        hi[i] = h; lo[i] = __float2bfloat16(v - __bfloat162float(h));
    }
}
__global__ void cvt_w_fc(const float* __restrict__ W,
                         __nv_bfloat16* __restrict__ hi, __nv_bfloat16* __restrict__ lo) {
    int i = blockIdx.x * blockDim.x + threadIdx.x;
    if (i < CHID * CHID) {
        int col = i >> 10, k = i & 1023;
        float v = W[(size_t)k * CHID + col];
        __nv_bfloat16 h = __float2bfloat16(v);
        hi[i] = h; lo[i] = __float2bfloat16(v - __bfloat162float(h));
    }
}

// ============================================================================
// mma.sync split-bf16 GEMM with cp.async double-buffered chunk loads.
// MODE 0: fp16 scatter [B,NH,S,DH] (scale applied); MODE 2: fp16 V^T; MODE 3: fp32
// ============================================================================
#define SPITCH 144
#define TILE_BYTES (128 * SPITCH)
#define GEMM_SMEM_BYTES (8 * TILE_BYTES)   // 2 buffers x 4 tiles

template<int MODE>
__global__ __launch_bounds__(256, 1) void gemm_mma(
    const __nv_bfloat16* __restrict__ Xh, const __nv_bfloat16* __restrict__ Xl,
    const __nv_bfloat16* __restrict__ Wh, const __nv_bfloat16* __restrict__ Wl,
    const float* __restrict__ bias, float* __restrict__ outf,
    __half* __restrict__ oh, float qscale)
{
    extern __shared__ char smem[];
    uint32_t sbase = smem_u32(smem);
    int tid = threadIdx.x, wid = tid >> 5, lid = tid & 31;
    int wm = wid & 1, wn = wid >> 1;
    int m0 = blockIdx.x * 128, n0 = blockIdx.y * 128;

    float C[4][4][4];
    #pragma unroll
    for (int i = 0; i < 4; i++)
        #pragma unroll
        for (int j = 0; j < 4; j++)
            #pragma unroll
            for (int r = 0; r < 4; r++) C[i][j][r] = 0.f;

    uint32_t a_row = wm * 64 + (lid & 15), a_koff = (lid >> 4) * 8;
    uint32_t b_n = wn * 32 + ((lid >> 4) * 8) + (lid & 7);
    uint32_t b_koff = ((lid >> 3) & 1) * 8;

    auto issue_chunk = [&](int c, int buf) {
        #pragma unroll
        for (int t = 0; t < 4; t++) {
            const __nv_bfloat16* src = (t == 0) ? Xh : (t == 1) ? Xl : (t == 2) ? Wh : Wl;
            const bool isA = (t < 2);
            uint32_t db = sbase + (uint32_t)(buf * 4 + t) * TILE_BYTES;
            #pragma unroll
            for (int p = 0; p < 4; p++) {
                int slot = tid + p * 256;
                int row = slot >> 3, i8 = slot & 7;
                int gr = (isA ? m0 : n0) + row;
                int sz = (!isA || gr < MROWS) ? 16 : 0;
                int grc = (isA && gr >= MROWS) ? (MROWS - 1) : gr;
                cpa16(db + row * SPITCH + i8 * 16,
                      src + (size_t)grc * CHID + c * 64 + i8 * 8, sz);
            }
        }
    };
    issue_chunk(0, 0);
    CPA_COMMIT();

    for (int c = 0; c < CHID / 64; c++) {
        int buf = c & 1;
        CPA_WAIT0();
        __syncthreads();
        if (c < CHID / 64 - 1) { issue_chunk(c + 1, buf ^ 1); CPA_COMMIT(); }
        uint32_t base = sbase + (uint32_t)buf * 4 * TILE_BYTES;
        #pragma unroll
        for (int ks = 0; ks < 4; ks++) {
            uint32_t Ah[4][4], Al[4][4], Bh[4][2], Bl[4][2];
            #pragma unroll
            for (int i = 0; i < 4; i++) {
                uint32_t off = (a_row + i * 16) * SPITCH + (ks * 16 + a_koff) * 2;
                ldsm4(Ah[i], base + 0 * TILE_BYTES + off);
                ldsm4(Al[i], base + 1 * TILE_BYTES + off);
            }
            #pragma unroll
            for (int j2 = 0; j2 < 2; j2++) {
                uint32_t off = (b_n + j2 * 16) * SPITCH + (ks * 16 + b_koff) * 2;
                uint32_t tmp[4];
                ldsm4(tmp, base + 2 * TILE_BYTES + off);
                Bh[j2*2][0] = tmp[0]; Bh[j2*2][1] = tmp[1];
                Bh[j2*2+1][0] = tmp[2]; Bh[j2*2+1][1] = tmp[3];
                ldsm4(tmp, base + 3 * TILE_BYTES + off);
                Bl[j2*2][0] = tmp[0]; Bl[j2*2][1] = tmp[1];
                Bl[j2*2+1][0] = tmp[2]; Bl[j2*2+1][1] = tmp[3];
            }
            #pragma unroll
            for (int i = 0; i < 4; i++)
                #pragma unroll
                for (int j = 0; j < 4; j++) {
                    mma16816(C[i][j], Ah[i], Bh[j]);
                    mma16816(C[i][j], Ah[i], Bl[j]);
                    mma16816(C[i][j], Al[i], Bh[j]);
                }
        }
    }
    int r = lid >> 2, cg = (lid & 3) * 2;
    #pragma unroll
    for (int i = 0; i < 4; i++) {
        int rows[2] = { m0 + wm*64 + i*16 + r, m0 + wm*64 + i*16 + r + 8 };
        #pragma unroll
        for (int j = 0; j < 4; j++) {
            int col = n0 + wn * 32 + j * 8 + cg;
            float b0 = bias[col], b1 = bias[col + 1];
            float vx[2] = { C[i][j][0] + b0, C[i][j][2] + b0 };
            float vy[2] = { C[i][j][1] + b1, C[i][j][3] + b1 };
            #pragma unroll
            for (int h = 0; h < 2; h++) {
                int row = rows[h];
                if (row >= MROWS) continue;
                if (MODE == 3) {
                    *(float2*)(outf + (size_t)row * CHID + col) = make_float2(vx[h], vy[h]);
                } else {
                    int bi = row / CS, s = row - bi * CS;
                    int n = col >> 6, d = col & 63;
                    float sx = vx[h] * qscale, sy = vy[h] * qscale;
                    if (MODE == 0) {
                        size_t a = (((size_t)(bi * CNH + n)) * CS + s) * CDH + d;
                        *(__half2*)(oh + a) = __floats2half2_rn(sx, sy);
                    } else {
                        size_t base = (size_t)(bi * CNH + n) * CDH;
                        oh[(base + d) * SPAD + s] = __float2half(sx);
                        oh[(base + d + 1) * SPAD + s] = __float2half(sy);
                    }
                }
            }
        }
    }
}

// ============================================================================
// Tensor-core flash attention + Shaw bias. Single-pass fp16 QK & PV.
// q-tile=128, warp-owned rows, 1 barrier per k-tile, register softmax state.
// ============================================================================
#define FP 144
#define OQ 0                    // 128 x 144 = 18432 (fp16 Q)
#define OKB 18432               // 2 buffers x (K 9216 + V 9216) = 36864
#define ORS 55296               // half [128][132] = 33792
#define OPV 89088               // float [129][68] = 35088
#define OPB 124176              // float [128][68] = 34816
#define FSM 158992

__global__ __launch_bounds__(256, 1) void flash_mma(
    const float* __restrict__ posk, const float* __restrict__ posv)
{
    extern __shared__ char sm[];
    uint32_t sb = smem_u32(sm);
    __half* Rs  = (__half*)(sm + ORS);
    float*  PVt = (float*)(sm + OPV);
    float*  Pb  = (float*)(sm + OPB);

    int qt = blockIdx.x, hn = blockIdx.y, bb = blockIdx.z;
    int q0 = qt * 128;
    size_t ho = ((size_t)(bb * CNH + hn)) * CS * CDH;
    size_t hv = ((size_t)(bb * CNH + hn)) * CDH * SPAD;
    int tid = threadIdx.x, wid = tid >> 5, lid = tid & 31;
    int qr = lid >> 2, qc = (lid & 3) * 2;
    int row0 = wid * 16 + qr, row1 = row0 + 8;
    int qg0 = q0 + row0, qg1 = q0 + row1;
    int wbase = q0 + wid * 16;

    auto issue_kv = [&](int kt2, uint32_t kb) {
        #pragma unroll
        for (int p = 0; p < 2; p++) {
            int slot = tid + p * 256;
            int r = slot >> 3, i8 = slot & 7;
            int kg = kt2 * 64 + r;
            int sz = (kg < CS) ? 16 : 0;
            int kgc = (kg < CS) ? kg : (CS - 1);
            cpa16(sb + kb + r * FP + i8 * 16,        g_kf + ho + (size_t)kgc * CDH + i8 * 8, sz);
            cpa16(sb + kb + 9216 + r * FP + i8 * 16, g_vf + hv + (size_t)r * SPAD + kt2 * 64 + i8 * 8, 16);
        }
    };
    issue_kv(0, OKB);
    CPA_COMMIT();

    // ---- prologue: Q tile, posk/8 -> PVt, q -> Pb, Rs table (fp16), posv ----
    #pragma unroll
    for (int p = 0; p < 4; p++) {
        int slot = tid + p * 256;
        int r = slot >> 3, i8 = slot & 7;
        int qg = q0 + r;
        uint4 v = make_uint4(0,0,0,0);
        if (qg < CS) v = ((const uint4*)(g_qf + ho + (size_t)qg * CDH))[i8];
        *(uint4*)(sm + OQ + r * FP + i8 * 16) = v;
    }
    for (int idx = tid; idx < NREL * 64; idx += 256)
        PVt[(idx >> 6) * 68 + (idx & 63)] = posk[idx] * 0.125f;
    __syncthreads();
    for (int idx = tid; idx < 128 * 64; idx += 256) {
        int r = idx >> 6, d = idx & 63;
        // Q tile holds q/8; reconstruct q. Rs = q . (posk/8) = (q.posk)/8
        Pb[r * 68 + d] = __half2float(*(__half*)(sm + OQ + r * FP + d * 2)) * 8.0f;
    }
    __syncthreads();
    for (int t = tid; t < 128 * 33; t += 256) {
        int qq = t / 33, jg = t - qq * 33, j0 = jg * 4;
        const float4* q4 = (const float4*)(Pb + qq * 68);
        if (jg < 32) {
            const float4 *p0 = (const float4*)(PVt + (j0+0)*68), *p1 = (const float4*)(PVt + (j0+1)*68);
            const float4 *p2 = (const float4*)(PVt + (j0+2)*68), *p3 = (const float4*)(PVt + (j0+3)*68);
            float a0=0,a1=0,a2=0,a3=0;
            #pragma unroll
            for (int d4 = 0; d4 < 16; d4++) {
                float4 qv = q4[d4]; float4 x;
                x=p0[d4]; a0+=qv.x*x.x+qv.y*x.y+qv.z*x.z+qv.w*x.w;
                x=p1[d4]; a1+=qv.x*x.x+qv.y*x.y+qv.z*x.z+qv.w*x.w;
                x=p2[d4]; a2+=qv.x*x.x+qv.y*x.y+qv.z*x.z+qv.w*x.w;
                x=p3[d4]; a3+=qv.x*x.x+qv.y*x.y+qv.z*x.z+qv.w*x.w;
            }
            Rs[qq*132+j0]   = __float2half(a0); Rs[qq*132+j0+1] = __float2half(a1);
            Rs[qq*132+j0+2] = __float2half(a2); Rs[qq*132+j0+3] = __float2half(a3);
        } else {
            const float4* p0 = (const float4*)(PVt + 128 * 68);
            float a0 = 0.f;
            #pragma unroll
            for (int d4 = 0; d4 < 16; d4++) {
                float4 qv = q4[d4], x = p0[d4];
                a0 += qv.x*x.x + qv.y*x.y + qv.z*x.z + qv.w*x.w;
            }
            Rs[qq * 132 + 128] = __float2half(a0);
        }
    }
    __syncthreads();
    for (int idx = tid; idx < NREL * 64; idx += 256)
        PVt[(idx >> 6) * 68 + (idx & 63)] = posv[idx];

    float rm0 = -1e30f, rm1 = -1e30f, rl0 = 0.f, rl1 = 0.f;
    float rL0 = 0.f, rL1 = 0.f, rH0 = 0.f, rH1 = 0.f;
    float O[8][4];
    #pragma unroll
    for (int nf = 0; nf < 8; nf++)
        #pragma unroll
        for (int c = 0; c < 4; c++) O[nf][c] = 0.f;

    uint32_t a_off = (uint32_t)((wid * 16 + (lid & 15)) * FP) + ((lid >> 4) * 8) * 2;
    uint32_t bk_row = ((lid >> 4) * 8) + (lid & 7);
    uint32_t bk_koff = ((lid >> 3) & 1) * 8;

    for (int kt = 0; kt < 24; kt++) {
        uint32_t kb = OKB + (kt & 1) * 18432;
        CPA_WAIT0();
        __syncthreads();
        if (kt < 23) { issue_kv(kt + 1, OKB + ((kt + 1) & 1) * 18432); CPA_COMMIT(); }

        // ---- S = QK^T (single fp16) ----
        float S[8][4];
        #pragma unroll
        for (int nf = 0; nf < 8; nf++)
            #pragma unroll
            for (int c = 0; c < 4; c++) S[nf][c] = 0.f;
        #pragma unroll
        for (int ks = 0; ks < 4; ks++) {
            uint32_t A[4];
            ldsm4(A, sb + OQ + a_off + ks * 32);
            #pragma unroll
            for (int j2 = 0; j2 < 4; j2++) {
                uint32_t t[4];
                ldsm4(t, sb + kb + (bk_row + j2 * 16) * FP + (ks * 16 + bk_koff) * 2);
                uint32_t B0[2] = { t[0], t[1] }, B1[2] = { t[2], t[3] };
                mma16816h(S[j2*2], A, B0);
                mma16816h(S[j2*2+1], A, B1);
            }
        }

        // ---- bias (fast path for fully-clipped tiles) + mask + quad max ----
        int tlo = kt * 64, thi = kt * 64 + 63;
        bool fully_lo = (thi - wbase <= -64);
        bool fully_hi = (tlo - (wbase + 15) >= 64);
        bool genpath = !(fully_lo || fully_hi);
        float m0v = -1e30f, m1v = -1e30f;
        if (!genpath) {
            int jc = fully_lo ? 0 : 128;
            float b0 = __half2float(Rs[row0 * 132 + jc]);
            float b1 = __half2float(Rs[row1 * 132 + jc]);
            #pragma unroll
            for (int nf = 0; nf < 8; nf++) {
                int kg0 = kt * 64 + nf * 8 + qc;
                float s0 = S[nf][0] + b0, s1 = S[nf][1] + b0;
                float s2 = S[nf][2] + b1, s3 = S[nf][3] + b1;
                if (kg0 >= CS)     { s0 = -1e30f; s2 = -1e30f; }
                if (kg0 + 1 >= CS) { s1 = -1e30f; s3 = -1e30f; }
                S[nf][0]=s0; S[nf][1]=s1; S[nf][2]=s2; S[nf][3]=s3;
                m0v = fmaxf(m0v, fmaxf(s0, s1));
                m1v = fmaxf(m1v, fmaxf(s2, s3));
            }
        } else {
            #pragma unroll
            for (int nf = 0; nf < 8; nf++) {
                int colb = nf * 8 + qc;
                int kg0 = kt * 64 + colb, kg1 = kg0 + 1;
                int j00 = min(max(kg0-qg0,-64),64)+64, j01 = min(max(kg1-qg0,-64),64)+64;
                int j10 = min(max(kg0-qg1,-64),64)+64, j11 = min(max(kg1-qg1,-64),64)+64;
                float s0 = S[nf][0] + __half2float(Rs[row0*132+j00]);
                float s1 = S[nf][1] + __half2float(Rs[row0*132+j01]);
                float s2 = S[nf][2] + __half2float(Rs[row1*132+j10]);
                float s3 = S[nf][3] + __half2float(Rs[row1*132+j11]);
                if (kg0 >= CS) { s0 = -1e30f; s2 = -1e30f; }
                if (kg1 >= CS) { s1 = -1e30f; s3 = -1e30f; }
                S[nf][0]=s0; S[nf][1]=s1; S[nf][2]=s2; S[nf][3]=s3;
                m0v = fmaxf(m0v, fmaxf(s0, s1));
                m1v = fmaxf(m1v, fmaxf(s2, s3));
            }
        }
        m0v = fmaxf(m0v, __shfl_xor_sync(~0u, m0v, 1)); m0v = fmaxf(m0v, __shfl_xor_sync(~0u, m0v, 2));
        m1v = fmaxf(m1v, __shfl_xor_sync(~0u, m1v, 1)); m1v = fmaxf(m1v, __shfl_xor_sync(~0u, m1v, 2));

        float mn0 = fmaxf(rm0, m0v), mn1 = fmaxf(rm1, m1v);
        float al0 = 1.f, al1 = 1.f;
        if (mn0 > rm0 || mn1 > rm1) {
            al0 = fexp(rm0 - mn0); al1 = fexp(rm1 - mn1);
            rm0 = mn0; rm1 = mn1;
            #pragma unroll
            for (int nf = 0; nf < 8; nf++) { O[nf][0]*=al0; O[nf][1]*=al0; O[nf][2]*=al1; O[nf][3]*=al1; }
        }

        int klo = max(0, wbase - 63 - kt * 64);
        int khi = min(64, wbase + 15 + 64 - kt * 64 + 1);
        bool pvband = (khi > klo);
        float s0a=0,s1a=0,l0a=0,l1a=0,h0a=0,h1a=0;
        uint32_t PA[4][4];
        #pragma unroll
        for (int nf = 0; nf < 8; nf++) {
            int colb = nf * 8 + qc;
            int kg = kt * 64 + colb;
            float p00 = fexp(S[nf][0]-mn0), p01 = fexp(S[nf][1]-mn0);
            float p10 = fexp(S[nf][2]-mn1), p11 = fexp(S[nf][3]-mn1);
            s0a += p00 + p01; s1a += p10 + p11;
            if (genpath) {
                int e0 = kg - qg0, e1 = kg - qg1;
                l0a += (e0<=-64?p00:0.f) + (e0+1<=-64?p01:0.f);
                h0a += (e0>= 64?p00:0.f) + (e0+1>= 64?p01:0.f);
                l1a += (e1<=-64?p10:0.f) + (e1+1<=-64?p11:0.f);
                h1a += (e1>= 64?p10:0.f) + (e1+1>= 64?p11:0.f);
                *(float2*)&Pb[row0*68+colb] = make_float2(p00, p01);
                *(float2*)&Pb[row1*68+colb] = make_float2(p10, p11);
            }
            int kc = nf >> 1, hx = (nf & 1) * 2;
            PA[kc][hx]   = packh2(p00, p01);
            PA[kc][hx+1] = packh2(p10, p11);
        }
        s0a += __shfl_xor_sync(~0u,s0a,1); s0a += __shfl_xor_sync(~0u,s0a,2);
        s1a += __shfl_xor_sync(~0u,s1a,1); s1a += __shfl_xor_sync(~0u,s1a,2);
        if (genpath) {
            l0a += __shfl_xor_sync(~0u,l0a,1); l0a += __shfl_xor_sync(~0u,l0a,2);
            l1a += __shfl_xor_sync(~0u,l1a,1); l1a += __shfl_xor_sync(~0u,l1a,2);
            h0a += __shfl_xor_sync(~0u,h0a,1); h0a += __shfl_xor_sync(~0u,h0a,2);
            h1a += __shfl_xor_sync(~0u,h1a,1); h1a += __shfl_xor_sync(~0u,h1a,2);
        } else if (fully_lo) { l0a = s0a; l1a = s1a; }
        else                 { h0a = s0a; h1a = s1a; }
        rl0 = rl0*al0 + s0a; rl1 = rl1*al1 + s1a;
        rL0 = rL0*al0 + l0a; rL1 = rL1*al1 + l1a;
        rH0 = rH0*al0 + h0a; rH1 = rH1*al1 + h1a;
        if (pvband) __syncwarp();

        // ---- O += P @ V (single fp16) ----
        #pragma unroll
        for (int kc = 0; kc < 4; kc++) {
            #pragma unroll
            for (int jd = 0; jd < 4; jd++) {
                uint32_t t[4];
                ldsm4(t, sb + kb + 9216 + (jd*16 + bk_row) * FP + (kc*16 + bk_koff) * 2);
                uint32_t B0[2] = { t[0], t[1] }, B1[2] = { t[2], t[3] };
                mma16816h(O[jd*2], PA[kc], B0);
                mma16816h(O[jd*2+1], PA[kc], B1);
            }
        }
        // ---- banded pos_v term ----
        if (pvband) {
            for (int k = klo; k < khi; k++) {
                int kg = kt * 64 + k;
                float p0 = Pb[row0*68+k], p1 = Pb[row1*68+k];
                int d0 = kg - qg0, d1 = kg - qg1;
                bool b0 = d0 > -64 && d0 < 64, b1 = d1 > -64 && d1 < 64;
                const float* r0p = PVt + (d0 + 64) * 68;
                const float* r1p = PVt + (d1 + 64) * 68;
                #pragma unroll
                for (int nf = 0; nf < 8; nf++) {
                    int col = nf * 8 + qc;
                    if (b0) { float2 v = *(const float2*)(r0p + col); O[nf][0] += p0*v.x; O[nf][1] += p0*v.y; }
                    if (b1) { float2 v = *(const float2*)(r1p + col); O[nf][2] += p1*v.x; O[nf][3] += p1*v.y; }
                }
            }
        }
    }

    // ---- epilogue: per-warp direct write ----
    float il0 = 1.f / rl0, il1 = 1.f / rl1;
    size_t ob0 = ((size_t)(bb * CS + qg0)) * CHID + hn * 64;
    size_t ob1 = ((size_t)(bb * CS + qg1)) * CHID + hn * 64;
    #pragma unroll
    for (int nf = 0; nf < 8; nf++) {
        int col = nf * 8 + qc;
        float2 v0 = *(float2*)&PVt[col];
        float2 v2 = *(float2*)&PVt[128*68+col];
        float o00 = (O[nf][0] + rL0*v0.x + rH0*v2.x) * il0;
        float o01 = (O[nf][1] + rL0*v0.y + rH0*v2.y) * il0;
        float o10 = (O[nf][2] + rL1*v0.x + rH1*v2.x) * il1;
        float o11 = (O[nf][3] + rL1*v0.y + rH1*v2.y) * il1;
        if (qg0 < CS) {
            __nv_bfloat16 hx = __float2bfloat16(o00), hy = __float2bfloat16(o01);
            *(__nv_bfloat162*)(g_xh + ob0 + col) = __halves2bfloat162(hx, hy);
            *(__nv_bfloat162*)(g_xl + ob0 + col) = __halves2bfloat162(
                __float2bfloat16(o00 - __bfloat162float(hx)),
                __float2bfloat16(o01 - __bfloat162float(hy)));
        }
        if (qg1 < CS) {
            __nv_bfloat16 hx = __float2bfloat16(o10), hy = __float2bfloat16(o11);
            *(__nv_bfloat162*)(g_xh + ob1 + col) = __halves2bfloat162(hx, hy);
            *(__nv_bfloat162*)(g_xl + ob1 + col) = __halves2bfloat162(
                __float2bfloat16(o10 - __bfloat162float(hx)),
                __float2bfloat16(o11 - __bfloat162float(hy)));
        }
    }
}

// ============================================================================
extern "C" void kernel_launch(void* const* d_in, const int* in_sizes, int n_in,
                              void* d_out, int out_size)
{
    const float* query = (const float*)d_in[0];
    const float* key   = (const float*)d_in[1];
    const float* value = (const float*)d_in[2];
    const float* Wq    = (const float*)d_in[3];
    const float* bq    = (const float*)d_in[4];
    const float* Wk    = (const float*)d_in[5];
    const float* bk    = (const float*)d_in[6];
    const float* Wv    = (const float*)d_in[7];
    const float* bv    = (const float*)d_in[8];
    const float* posk  = (const float*)d_in[9];
    const float* posv  = (const float*)d_in[10];
    const float* Wfc   = (const float*)d_in[11];
    const float* bfc   = (const float*)d_in[12];
    float* out = (float*)d_out;

    __nv_bfloat16 *xh, *xl, *wh, *wl;
    __half *qf, *kf, *vf;
    cudaGetSymbolAddress((void**)&xh, g_xh);
    cudaGetSymbolAddress((void**)&xl, g_xl);
    cudaGetSymbolAddress((void**)&wh, g_wh);
    cudaGetSymbolAddress((void**)&wl, g_wl);
    cudaGetSymbolAddress((void**)&qf, g_qf);
    cudaGetSymbolAddress((void**)&kf, g_kf);
    cudaGetSymbolAddress((void**)&vf, g_vf);

    cudaFuncSetAttribute(gemm_mma<0>, cudaFuncAttributeMaxDynamicSharedMemorySize, GEMM_SMEM_BYTES);
    cudaFuncSetAttribute(gemm_mma<2>, cudaFuncAttributeMaxDynamicSharedMemorySize, GEMM_SMEM_BYTES);
    cudaFuncSetAttribute(gemm_mma<3>, cudaFuncAttributeMaxDynamicSharedMemorySize, GEMM_SMEM_BYTES);
    cudaFuncSetAttribute(flash_mma, cudaFuncAttributeMaxDynamicSharedMemorySize, FSM);

    const int nX = MROWS * CHID, nW = CHID * CHID;
    dim3 ggrid((MROWS + 127) / 128, CHID / 128);

    cvt_split<<<(nX + 255) / 256, 256>>>(query, xh, xl, nX);
    cvt_w_proj<<<(nW + 255) / 256, 256>>>(Wq, wh, wl);
    gemm_mma<0><<<ggrid, 256, GEMM_SMEM_BYTES>>>(xh, xl, wh, wl, bq, nullptr, qf, 0.125f);

    cvt_split<<<(nX + 255) / 256, 256>>>(key, xh, xl, nX);
    cvt_w_proj<<<(nW + 255) / 256, 256>>>(Wk, wh, wl);
    gemm_mma<0><<<ggrid, 256, GEMM_SMEM_BYTES>>>(xh, xl, wh, wl, bk, nullptr, kf, 1.f);

    cvt_split<<<(nX + 255) / 256, 256>>>(value, xh, xl, nX);
    cvt_w_proj<<<(nW + 255) / 256, 256>>>(Wv, wh, wl);
    gemm_mma<2><<<ggrid, 256, GEMM_SMEM_BYTES>>>(xh, xl, wh, wl, bv, nullptr, vf, 1.f);

    flash_mma<<<dim3(12, CNH, CB), 256, FSM>>>(posk, posv);

    cvt_w_fc<<<(nW + 255) / 256, 256>>>(Wfc, wh, wl);
    gemm_mma<3><<<ggrid, 256, GEMM_SMEM_BYTES>>>(xh, xl, wh, wl, bfc, out, nullptr, 1.f);
}